// round 13
// baseline (speedup 1.0000x reference)
#include <cuda_runtime.h>
#include <cuda_fp16.h>
#include <math.h>

// ---------------- problem constants ----------------
constexpr int NN = 20000;
constexpr int EE = 320000;
constexpr int RB = 20;    // NRBF
constexpr float PI_F = 3.14159265358979323846f;
constexpr float EPS3 = 3e-15f;

// ---------------- device scratch ----------------
__device__ float g_rbf [(size_t)EE * RB];
__device__ float g_env [EE];
__device__ float g_unit[(size_t)EE * 3];
__device__ float g_eij [(size_t)EE * 128];
__device__ float g_s   [(size_t)NN * 128];
__device__ float g_v0  [(size_t)NN * 384];
__device__ float g_v1  [(size_t)NN * 384];
__device__ float g_phi [(size_t)NN * 384];
__device__ float g_h1  [(size_t)NN * 128];
__device__ float g_uv  [(size_t)NN * 384];
__device__ float g_dot [(size_t)NN * 128];
__device__ float g_stk [(size_t)NN * 256];
__device__ float g_spl [(size_t)NN * 384];
__device__ float g_t   [(size_t)NN * 256];
// CSR by src
__device__ int g_rowptr[NN + 1];
__device__ int g_cursor[NN];
__device__ int g_perm  [EE];

__device__ __forceinline__ float swish(float x) {
    return x / (1.f + expf(-x));
}

__device__ __forceinline__ void split_h(float x, __half& hi, __half& lo) {
    hi = __float2half_rn(x);
    lo = __float2half_rn(x - __half2float(hi));
}

__device__ __forceinline__ void hmma(float* d, const unsigned* a, const unsigned* b) {
    asm volatile(
        "mma.sync.aligned.m16n8k16.row.col.f32.f16.f16.f32 "
        "{%0,%1,%2,%3}, {%4,%5,%6,%7}, {%8,%9}, {%0,%1,%2,%3};"
        : "+f"(d[0]), "+f"(d[1]), "+f"(d[2]), "+f"(d[3])
        : "r"(a[0]), "r"(a[1]), "r"(a[2]), "r"(a[3]), "r"(b[0]), "r"(b[1]));
}

__device__ __forceinline__ unsigned sm_u32(const void* p) {
    unsigned a;
    asm("{ .reg .u64 t; cvta.to.shared.u64 t, %1; cvt.u32.u64 %0, t; }"
        : "=r"(a) : "l"(p));
    return a;
}

#define LDSM4(r0, r1, r2, r3, a) \
    asm volatile("ldmatrix.sync.aligned.m8n8.x4.shared.b16 {%0,%1,%2,%3}, [%4];" \
                 : "=r"(r0), "=r"(r1), "=r"(r2), "=r"(r3) : "r"(a))

// ---------------- init ----------------
__global__ void init_kernel(const float* __restrict__ emb, const int* __restrict__ z,
                            float* __restrict__ out) {
    int stride = gridDim.x * blockDim.x;
    for (int i = blockIdx.x * blockDim.x + threadIdx.x; i < NN * 384; i += stride) {
        g_v0[i] = 0.f;
        if (i < NN * 128) {
            int n = i >> 7, f = i & 127;
            g_s[i] = emb[z[n] * 128 + f];
        }
        if (i < NN * 3) out[i] = 0.f;
    }
}

// ---------------- CSR build ----------------
__global__ void zero_rowptr() {
    int i = blockIdx.x * blockDim.x + threadIdx.x;
    if (i <= NN) g_rowptr[i] = 0;
}
__global__ void hist_kernel(const int* __restrict__ nbrs) {
    int e = blockIdx.x * blockDim.x + threadIdx.x;
    if (e < EE) atomicAdd(&g_rowptr[nbrs[2 * e] + 1], 1);
}
__global__ void scan_kernel() {
    __shared__ int sm[1024];
    __shared__ int carry;
    int t = threadIdx.x;
    if (t == 0) carry = 0;
    __syncthreads();
    int nch = (NN + 1 + 1023) / 1024;
    for (int c = 0; c < nch; c++) {
        int i = c * 1024 + t;
        int v = (i <= NN) ? g_rowptr[i] : 0;
        sm[t] = v;
        __syncthreads();
        #pragma unroll
        for (int off = 1; off < 1024; off <<= 1) {
            int x = (t >= off) ? sm[t - off] : 0;
            __syncthreads();
            sm[t] += x;
            __syncthreads();
        }
        if (i <= NN) {
            int val = sm[t] + carry;
            g_rowptr[i] = val;
            if (i < NN) g_cursor[i] = val;
        }
        int total = sm[1023];
        __syncthreads();
        if (t == 0) carry += total;
        __syncthreads();
    }
}
__global__ void scatter_kernel(const int* __restrict__ nbrs) {
    int e = blockIdx.x * blockDim.x + threadIdx.x;
    if (e < EE) {
        int pos = atomicAdd(&g_cursor[nbrs[2 * e]], 1);
        g_perm[pos] = e;
    }
}

// ---------------- per-edge geometry ----------------
__global__ void prep_kernel(const float* __restrict__ xyz, const int* __restrict__ nbrs) {
    int e = blockIdx.x * blockDim.x + threadIdx.x;
    if (e >= EE) return;
    int s = nbrs[2 * e], d = nbrs[2 * e + 1];
    float dx = xyz[d * 3 + 0] - xyz[s * 3 + 0];
    float dy = xyz[d * 3 + 1] - xyz[s * 3 + 1];
    float dz = xyz[d * 3 + 2] - xyz[s * 3 + 2];
    float d2 = dx * dx + dy * dy + dz * dz + EPS3;
    float dist = sqrtf(d2);
    float inv = 1.f / dist;
    g_unit[(size_t)e * 3 + 0] = dx * inv;
    g_unit[(size_t)e * 3 + 1] = dy * inv;
    g_unit[(size_t)e * 3 + 2] = dz * inv;
    float env = (dist < 5.f) ? 0.5f * (cosf(dist * (PI_F / 5.f)) + 1.f) : 0.f;
    g_env[e] = env;
    float base = dist * (PI_F / 5.f);
    #pragma unroll
    for (int k = 1; k <= RB; k++) {
        g_rbf[(size_t)e * RB + (k - 1)] = sinf(base * (float)k) * inv;
    }
}

// ================ generic HMMA GEMM (ldmatrix inner loop) ================
// RBF0: epilogue adds (rbf@de_w + de_b)*env (the e_ij init term) instead of ACCUM.
constexpr int HP = 72;
template<int K, bool GATHER_SWISH, bool SWISH_OUT, bool ACCUM, bool RBF0>
__global__ void __launch_bounds__(256, 2)
hmma_gemm(const float* __restrict__ Ain, const float* __restrict__ W, int ldw,
          const float* __restrict__ bias, float bias_scale, float* __restrict__ C,
          const int* __restrict__ nbrs, int M,
          const float* __restrict__ rbfp, const float* __restrict__ envp,
          const float* __restrict__ dew,  const float* __restrict__ deb) {
    extern __shared__ __align__(16) __half hsm[];
    __half* Ah = hsm;
    __half* Al = Ah + 128 * HP;
    __half* Bh = Al + 128 * HP;
    __half* Bl = Bh + 128 * HP;
    __shared__ int s_src[128], s_dst[128];
    __shared__ __align__(16) float s_dew [RBF0 ? RB * 128 : 1];
    __shared__ __align__(16) float s_rbfv[RBF0 ? 128 * RB : 1];
    __shared__ float s_envv[RBF0 ? 128 : 1];
    __shared__ float s_deb [RBF0 ? 128 : 1];

    int tid = threadIdx.x;
    int wid = tid >> 5, lane = tid & 31;
    int g = lane >> 2, tq = lane & 3;
    int wm0 = (wid & 3) * 32;
    int n0w = (wid >> 2) * 64;
    int m0b = blockIdx.x * 128;
    int col0 = blockIdx.y * 128;

    // ldmatrix lane-address components
    unsigned ah_base = sm_u32(Ah), al_base = sm_u32(Al);
    unsigned bh_base = sm_u32(Bh), bl_base = sm_u32(Bl);
    int a_row = lane & 15, a_col = (lane >> 4) << 3;
    int b_row = ((lane >> 4) << 3) + (lane & 7);
    int b_col = ((lane >> 3) & 1) << 3;

    if (GATHER_SWISH && tid < 128) {
        int m = m0b + tid;
        s_src[tid] = (m < M) ? nbrs[2 * m] : 0;
        s_dst[tid] = (m < M) ? nbrs[2 * m + 1] : 0;
    }
    if (RBF0) {
        for (int i = tid; i < RB * 128; i += 256) s_dew[i] = dew[i];
        for (int idx = tid; idx < 128 * 5; idx += 256) {
            int r = idx / 5, q = idx - r * 5;
            ((float4*)&s_rbfv[r * RB])[q] =
                ((const float4*)&rbfp[(size_t)(m0b + r) * RB])[q];
        }
        if (tid < 128) {
            s_envv[tid] = envp[m0b + tid];
            s_deb[tid]  = deb[tid];
        }
    }

    float acc[2][8][4];
    #pragma unroll
    for (int mi = 0; mi < 2; mi++)
        #pragma unroll
        for (int ni = 0; ni < 8; ni++)
            #pragma unroll
            for (int j = 0; j < 4; j++) acc[mi][ni][j] = 0.f;

    constexpr int NCH = K / 64;
    for (int kc = 0; kc < NCH; kc++) {
        __syncthreads();
        for (int idx = tid; idx < 128 * 16; idx += 256) {
            int r = idx >> 4, k = (idx & 15) * 4;
            int m = m0b + r;
            float x[4] = {0.f, 0.f, 0.f, 0.f};
            if (m < M) {
                if (GATHER_SWISH) {
                    float4 a = *(const float4*)&Ain[(size_t)s_src[r] * K + kc * 64 + k];
                    float4 b = *(const float4*)&Ain[(size_t)s_dst[r] * K + kc * 64 + k];
                    x[0] = swish(a.x + b.x); x[1] = swish(a.y + b.y);
                    x[2] = swish(a.z + b.z); x[3] = swish(a.w + b.w);
                } else {
                    float4 a = *(const float4*)&Ain[(size_t)m * K + kc * 64 + k];
                    x[0] = a.x; x[1] = a.y; x[2] = a.z; x[3] = a.w;
                }
            }
            #pragma unroll
            for (int j = 0; j < 4; j++) {
                __half hi, lo;
                split_h(x[j], hi, lo);
                Ah[r * HP + k + j] = hi;
                Al[r * HP + k + j] = lo;
            }
        }
        for (int idx = tid; idx < 128 * 16; idx += 256) {
            int n = idx & 127, kl = (idx >> 7) * 4;
            #pragma unroll
            for (int j = 0; j < 4; j++) {
                float w = W[(size_t)(kc * 64 + kl + j) * ldw + col0 + n];
                __half hi, lo;
                split_h(w, hi, lo);
                Bh[n * HP + kl + j] = hi;
                Bl[n * HP + kl + j] = lo;
            }
        }
        __syncthreads();

        #pragma unroll
        for (int ks = 0; ks < 4; ks++) {
            int kl = ks * 16;
            unsigned ah[2][4], al[2][4];
            #pragma unroll
            for (int mi = 0; mi < 2; mi++) {
                unsigned off = ((unsigned)((wm0 + mi * 16 + a_row) * HP + kl + a_col)) * 2u;
                LDSM4(ah[mi][0], ah[mi][1], ah[mi][2], ah[mi][3], ah_base + off);
                LDSM4(al[mi][0], al[mi][1], al[mi][2], al[mi][3], al_base + off);
            }
            #pragma unroll
            for (int nip = 0; nip < 4; nip++) {
                unsigned boff = ((unsigned)((n0w + nip * 16 + b_row) * HP + kl + b_col)) * 2u;
                unsigned bh2[4], bl2[4];
                LDSM4(bh2[0], bh2[1], bh2[2], bh2[3], bh_base + boff);
                LDSM4(bl2[0], bl2[1], bl2[2], bl2[3], bl_base + boff);
                #pragma unroll
                for (int mi = 0; mi < 2; mi++) {
                    hmma(acc[mi][2 * nip],     ah[mi], &bh2[0]);
                    hmma(acc[mi][2 * nip],     ah[mi], &bl2[0]);
                    hmma(acc[mi][2 * nip],     al[mi], &bh2[0]);
                    hmma(acc[mi][2 * nip + 1], ah[mi], &bh2[2]);
                    hmma(acc[mi][2 * nip + 1], ah[mi], &bl2[2]);
                    hmma(acc[mi][2 * nip + 1], al[mi], &bh2[2]);
                }
            }
        }
    }

    #pragma unroll
    for (int mi = 0; mi < 2; mi++) {
        #pragma unroll
        for (int ni = 0; ni < 8; ni++) {
            int col = n0w + ni * 8 + 2 * tq;
            float2 bb = *(const float2*)&bias[col0 + col];
            bb.x *= bias_scale; bb.y *= bias_scale;
            #pragma unroll
            for (int h = 0; h < 2; h++) {
                int r = wm0 + mi * 16 + g + h * 8;
                int m = m0b + r;
                if (m >= M) continue;
                float2 o;
                o.x = acc[mi][ni][2 * h + 0] + bb.x;
                o.y = acc[mi][ni][2 * h + 1] + bb.y;
                if (SWISH_OUT) { o.x = swish(o.x); o.y = swish(o.y); }
                size_t ci = (size_t)m * ldw + col0 + col;
                if (RBF0) {
                    float dx = s_deb[col], dy = s_deb[col + 1];
                    const float* rrow = &s_rbfv[r * RB];
                    #pragma unroll
                    for (int k = 0; k < RB; k++) {
                        float rv = rrow[k];
                        dx = fmaf(rv, s_dew[k * 128 + col],     dx);
                        dy = fmaf(rv, s_dew[k * 128 + col + 1], dy);
                    }
                    float ev = s_envv[r];
                    o.x += ev * dx;
                    o.y += ev * dy;
                } else if (ACCUM) {
                    float2 old = *(const float2*)&C[ci];
                    o.x += old.x; o.y += old.y;
                }
                *(float2*)&C[ci] = o;
            }
        }
    }
}

// ---------------- CSR message pass: smem-staged edge metadata ----------------
constexpr int ETILE = 32;
__global__ void __launch_bounds__(128)
msg2_kernel(const int* __restrict__ nbrs, const float* __restrict__ dw,
            const float* __restrict__ db, int sel) {
    __shared__ int   s_dst[ETILE];
    __shared__ float s_env[ETILE];
    __shared__ float s_unit[ETILE][4];
    __shared__ __align__(16) float s_rbf[ETILE][RB];

    int n = blockIdx.x;
    int t = threadIdx.x;

    float dwr0[RB], dwr1[RB], dwr2[RB];
    #pragma unroll
    for (int k = 0; k < RB; k++) {
        dwr0[k] = dw[k * 384 + t];
        dwr1[k] = dw[k * 384 + t + 128];
        dwr2[k] = dw[k * 384 + t + 256];
    }
    float db0 = db[t], db1 = db[t + 128], db2 = db[t + 256];

    const float* vold = sel ? g_v1 : g_v0;
    float*       vnew = sel ? g_v0 : g_v1;

    int start = g_rowptr[n], end = g_rowptr[n + 1];
    float accs = 0.f, av0 = 0.f, av1 = 0.f, av2 = 0.f;

    for (int tile = start; tile < end; tile += ETILE) {
        int m = min(ETILE, end - tile);
        __syncthreads();
        if (t < m) {
            int e = g_perm[tile + t];
            s_dst[t] = nbrs[2 * e + 1];
            s_env[t] = g_env[e];
            s_unit[t][0] = g_unit[(size_t)e * 3 + 0];
            s_unit[t][1] = g_unit[(size_t)e * 3 + 1];
            s_unit[t][2] = g_unit[(size_t)e * 3 + 2];
        }
        for (int idx = t; idx < m * 5; idx += 128) {
            int le = idx / 5, q = idx - le * 5;
            int e = g_perm[tile + le];
            ((float4*)s_rbf[le])[q] = ((const float4*)&g_rbf[(size_t)e * RB])[q];
        }
        __syncthreads();

        for (int le = 0; le < m; le++) {
            const float4* rb4 = (const float4*)s_rbf[le];
            float4 r0 = rb4[0], r1 = rb4[1], r2 = rb4[2], r3 = rb4[3], r4 = rb4[4];
            float rb[RB] = {r0.x, r0.y, r0.z, r0.w, r1.x, r1.y, r1.z, r1.w,
                            r2.x, r2.y, r2.z, r2.w, r3.x, r3.y, r3.z, r3.w,
                            r4.x, r4.y, r4.z, r4.w};
            float a0 = db0, a1 = db1, a2 = db2;
            #pragma unroll
            for (int k = 0; k < RB; k++) {
                a0 = fmaf(rb[k], dwr0[k], a0);
                a1 = fmaf(rb[k], dwr1[k], a1);
                a2 = fmaf(rb[k], dwr2[k], a2);
            }
            float env = s_env[le];
            a0 *= env; a1 *= env; a2 *= env;

            int dst = s_dst[le];
            const float* ph = g_phi + (size_t)dst * 384;
            float s0 = ph[t] * a0;
            float s1 = ph[t + 128] * a1;
            float s2 = ph[t + 256] * a2;
            accs += s1;

            const float* vo = vold + (size_t)dst * 384 + 3 * t;
            av0 += fmaf(s0, vo[0], s2 * s_unit[le][0]);
            av1 += fmaf(s0, vo[1], s2 * s_unit[le][1]);
            av2 += fmaf(s0, vo[2], s2 * s_unit[le][2]);
        }
    }

    g_s[(size_t)n * 128 + t] += accs;
    const float* vs = vold + (size_t)n * 384 + 3 * t;
    float*       vp = vnew + (size_t)n * 384 + 3 * t;
    vp[0] = vs[0] + av0;
    vp[1] = vs[1] + av1;
    vp[2] = vs[2] + av2;
}

// ---------------- update stage 1 ----------------
constexpr int TA = 8;
__global__ void __launch_bounds__(128)
upd1_kernel(const float* __restrict__ U, const float* __restrict__ Vw, int sel) {
    __shared__ __align__(16) float v_s[TA * 384];
    int t = threadIdx.x;
    int n0 = blockIdx.x * TA;
    const float* vcur = sel ? g_v1 : g_v0;

    for (int i = t; i < TA * 384; i += 128) {
        size_t gi = (size_t)n0 * 384 + i;
        v_s[i] = (gi < (size_t)NN * 384) ? vcur[gi] : 0.f;
    }
    __syncthreads();

    float uv[TA][3], vv[TA][3];
    #pragma unroll
    for (int a = 0; a < TA; a++)
        #pragma unroll
        for (int d = 0; d < 3; d++) { uv[a][d] = 0.f; vv[a][d] = 0.f; }

    for (int f4 = 0; f4 < 32; f4++) {
        float u0 = U[(f4 * 4 + 0) * 128 + t];
        float u1 = U[(f4 * 4 + 1) * 128 + t];
        float u2 = U[(f4 * 4 + 2) * 128 + t];
        float u3 = U[(f4 * 4 + 3) * 128 + t];
        float w0 = Vw[(f4 * 4 + 0) * 128 + t];
        float w1 = Vw[(f4 * 4 + 1) * 128 + t];
        float w2 = Vw[(f4 * 4 + 2) * 128 + t];
        float w3 = Vw[(f4 * 4 + 3) * 128 + t];
        #pragma unroll
        for (int a = 0; a < TA; a++) {
            const float4* vp = reinterpret_cast<const float4*>(&v_s[a * 384 + f4 * 12]);
            float4 p0 = vp[0], p1 = vp[1], p2 = vp[2];
            uv[a][0] = fmaf(p0.x, u0, fmaf(p0.w, u1, fmaf(p1.z, u2, fmaf(p2.y, u3, uv[a][0]))));
            uv[a][1] = fmaf(p0.y, u0, fmaf(p1.x, u1, fmaf(p1.w, u2, fmaf(p2.z, u3, uv[a][1]))));
            uv[a][2] = fmaf(p0.z, u0, fmaf(p1.y, u1, fmaf(p2.x, u2, fmaf(p2.w, u3, uv[a][2]))));
            vv[a][0] = fmaf(p0.x, w0, fmaf(p0.w, w1, fmaf(p1.z, w2, fmaf(p2.y, w3, vv[a][0]))));
            vv[a][1] = fmaf(p0.y, w0, fmaf(p1.x, w1, fmaf(p1.w, w2, fmaf(p2.z, w3, vv[a][1]))));
            vv[a][2] = fmaf(p0.z, w0, fmaf(p1.y, w1, fmaf(p2.x, w2, fmaf(p2.w, w3, vv[a][2]))));
        }
    }

    #pragma unroll
    for (int a = 0; a < TA; a++) {
        int n = n0 + a;
        if (n >= NN) break;
        float dt = uv[a][0] * vv[a][0] + uv[a][1] * vv[a][1] + uv[a][2] * vv[a][2];
        float vn = sqrtf(vv[a][0] * vv[a][0] + vv[a][1] * vv[a][1] + vv[a][2] * vv[a][2] + EPS3);
        g_uv[(size_t)n * 384 + 3 * t + 0] = uv[a][0];
        g_uv[(size_t)n * 384 + 3 * t + 1] = uv[a][1];
        g_uv[(size_t)n * 384 + 3 * t + 2] = uv[a][2];
        g_dot[(size_t)n * 128 + t] = dt;
        g_stk[(size_t)n * 256 + t] = g_s[(size_t)n * 128 + t];
        g_stk[(size_t)n * 256 + 128 + t] = vn;
    }
}

// ---------------- update apply ----------------
__global__ void apply_kernel(int sel) {
    int i = blockIdx.x * blockDim.x + threadIdx.x;
    if (i >= NN * 128) return;
    int n = i >> 7, g = i & 127;
    float avv = g_spl[(size_t)n * 384 + g];
    float asv = g_spl[(size_t)n * 384 + 128 + g];
    float ass = g_spl[(size_t)n * 384 + 256 + g];
    float* v = (sel ? g_v1 : g_v0) + (size_t)n * 384 + 3 * g;
    const float* uv = g_uv + (size_t)n * 384 + 3 * g;
    v[0] += uv[0] * avv;
    v[1] += uv[1] * avv;
    v[2] += uv[2] * avv;
    g_s[i] += g_dot[i] * asv + ass;
}

// ================ HMMA fused readout (ldmatrix inner loop) ================
constexpr int HP2 = 136;
__global__ void __launch_bounds__(256)
readout_mma(const float* __restrict__ W1, const float* __restrict__ b1,
            const float* __restrict__ w2, const float* __restrict__ b2,
            const int* __restrict__ nbrs, float* __restrict__ out) {
    extern __shared__ __align__(16) __half hsm[];
    __half* Ah = hsm;
    __half* Al = Ah + 128 * HP2;
    __half* Bh = Al + 128 * HP2;
    __half* Bl = Bh + 128 * HP2;
    __shared__ float red[128][2];

    int tid = threadIdx.x;
    int wid = tid >> 5, lane = tid & 31;
    int g = lane >> 2, tq = lane & 3;
    int m0 = (wid & 3) * 32;
    int n0w = (wid >> 2) * 64;
    int nw = wid >> 2;
    int e0 = blockIdx.x * 128;

    unsigned ah_base = sm_u32(Ah), al_base = sm_u32(Al);
    unsigned bh_base = sm_u32(Bh), bl_base = sm_u32(Bl);
    int a_row = lane & 15, a_col = (lane >> 4) << 3;
    int b_row = ((lane >> 4) << 3) + (lane & 7);
    int b_col = ((lane >> 3) & 1) << 3;

    for (int idx = tid; idx < 128 * 32; idx += 256) {
        int e = idx >> 5, k = (idx & 31) * 4;
        float4 a = *(const float4*)&g_eij[(size_t)(e0 + e) * 128 + k];
        float x[4] = {a.x, a.y, a.z, a.w};
        #pragma unroll
        for (int j = 0; j < 4; j++) {
            __half hi, lo;
            split_h(x[j], hi, lo);
            Ah[e * HP2 + k + j] = hi;
            Al[e * HP2 + k + j] = lo;
        }
    }

    float rs[2][2] = {{0.f, 0.f}, {0.f, 0.f}};

    for (int nc = 0; nc < 2; nc++) {
        __syncthreads();
        for (int idx = tid; idx < 128 * 32; idx += 256) {
            int n = idx & 127, k = (idx >> 7) * 4;
            #pragma unroll
            for (int j = 0; j < 4; j++) {
                float w = W1[(size_t)(k + j) * 256 + nc * 128 + n];
                __half hi, lo;
                split_h(w, hi, lo);
                Bh[n * HP2 + k + j] = hi;
                Bl[n * HP2 + k + j] = lo;
            }
        }
        __syncthreads();

        float acc[2][8][4];
        #pragma unroll
        for (int mi = 0; mi < 2; mi++)
            #pragma unroll
            for (int ni = 0; ni < 8; ni++)
                #pragma unroll
                for (int j = 0; j < 4; j++) acc[mi][ni][j] = 0.f;

        #pragma unroll
        for (int ks = 0; ks < 8; ks++) {
            int kl = ks * 16;
            unsigned ah[2][4], al[2][4];
            #pragma unroll
            for (int mi = 0; mi < 2; mi++) {
                unsigned off = ((unsigned)((m0 + mi * 16 + a_row) * HP2 + kl + a_col)) * 2u;
                LDSM4(ah[mi][0], ah[mi][1], ah[mi][2], ah[mi][3], ah_base + off);
                LDSM4(al[mi][0], al[mi][1], al[mi][2], al[mi][3], al_base + off);
            }
            #pragma unroll
            for (int nip = 0; nip < 4; nip++) {
                unsigned boff = ((unsigned)((n0w + nip * 16 + b_row) * HP2 + kl + b_col)) * 2u;
                unsigned bh2[4], bl2[4];
                LDSM4(bh2[0], bh2[1], bh2[2], bh2[3], bh_base + boff);
                LDSM4(bl2[0], bl2[1], bl2[2], bl2[3], bl_base + boff);
                #pragma unroll
                for (int mi = 0; mi < 2; mi++) {
                    hmma(acc[mi][2 * nip],     ah[mi], &bh2[0]);
                    hmma(acc[mi][2 * nip],     ah[mi], &bl2[0]);
                    hmma(acc[mi][2 * nip],     al[mi], &bh2[0]);
                    hmma(acc[mi][2 * nip + 1], ah[mi], &bh2[2]);
                    hmma(acc[mi][2 * nip + 1], ah[mi], &bl2[2]);
                    hmma(acc[mi][2 * nip + 1], al[mi], &bh2[2]);
                }
            }
        }

        #pragma unroll
        for (int mi = 0; mi < 2; mi++) {
            #pragma unroll
            for (int ni = 0; ni < 8; ni++) {
                int c = nc * 128 + n0w + ni * 8 + 2 * tq;
                float2 bb = *(const float2*)&b1[c];
                float2 ww = *(const float2*)&w2[c];
                rs[mi][0] += swish(acc[mi][ni][0] + bb.x) * ww.x
                           + swish(acc[mi][ni][1] + bb.y) * ww.y;
                rs[mi][1] += swish(acc[mi][ni][2] + bb.x) * ww.x
                           + swish(acc[mi][ni][3] + bb.y) * ww.y;
            }
        }
    }

    #pragma unroll
    for (int mi = 0; mi < 2; mi++) {
        #pragma unroll
        for (int h = 0; h < 2; h++) {
            float v = rs[mi][h];
            v += __shfl_xor_sync(0xffffffff, v, 1);
            v += __shfl_xor_sync(0xffffffff, v, 2);
            rs[mi][h] = v;
        }
    }
    if (tq == 0) {
        red[m0 + g][nw]          = rs[0][0];
        red[m0 + g + 8][nw]      = rs[0][1];
        red[m0 + 16 + g][nw]     = rs[1][0];
        red[m0 + 16 + g + 8][nw] = rs[1][1];
    }
    __syncthreads();

    if (tid < 128) {
        int e = e0 + tid;
        float s = red[tid][0] + red[tid][1] + b2[0];
        int src = nbrs[2 * e], dst = nbrs[2 * e + 1];
        float fx = s * g_unit[(size_t)e * 3 + 0];
        float fy = s * g_unit[(size_t)e * 3 + 1];
        float fz = s * g_unit[(size_t)e * 3 + 2];
        atomicAdd(&out[src * 3 + 0], fx);
        atomicAdd(&out[src * 3 + 1], fy);
        atomicAdd(&out[src * 3 + 2], fz);
        atomicAdd(&out[dst * 3 + 0], -fx);
        atomicAdd(&out[dst * 3 + 1], -fy);
        atomicAdd(&out[dst * 3 + 2], -fz);
    }
}

// ---------------- host launcher ----------------
extern "C" void kernel_launch(void* const* d_in, const int* in_sizes, int n_in,
                              void* d_out, int out_size) {
    const float* xyz     = (const float*)d_in[0];
    const int*   z       = (const int*)  d_in[1];
    const int*   nbrs    = (const int*)  d_in[2];
    const float* emb     = (const float*)d_in[3];
    const float* de_w    = (const float*)d_in[4];
    const float* de_b    = (const float*)d_in[5];
    const float* msg_w1  = (const float*)d_in[6];
    const float* msg_b1  = (const float*)d_in[7];
    const float* msg_w2  = (const float*)d_in[8];
    const float* msg_b2  = (const float*)d_in[9];
    const float* msg_dw  = (const float*)d_in[10];
    const float* msg_db  = (const float*)d_in[11];
    const float* upd_u   = (const float*)d_in[12];
    const float* upd_v   = (const float*)d_in[13];
    const float* upd_w1  = (const float*)d_in[14];
    const float* upd_b1  = (const float*)d_in[15];
    const float* upd_w2  = (const float*)d_in[16];
    const float* upd_b2  = (const float*)d_in[17];
    const float* edge_w1 = (const float*)d_in[18];
    const float* edge_b1 = (const float*)d_in[19];
    const float* edge_w2 = (const float*)d_in[20];
    const float* edge_b2 = (const float*)d_in[21];
    const float* ro_w1   = (const float*)d_in[22];
    const float* ro_b1   = (const float*)d_in[23];
    const float* ro_w2   = (const float*)d_in[24];
    const float* ro_b2   = (const float*)d_in[25];
    float* out = (float*)d_out;

    float *p_rbf, *p_env, *p_eij, *p_s, *p_phi, *p_h1, *p_stk, *p_spl, *p_t;
    cudaGetSymbolAddress((void**)&p_rbf,  g_rbf);
    cudaGetSymbolAddress((void**)&p_env,  g_env);
    cudaGetSymbolAddress((void**)&p_eij,  g_eij);
    cudaGetSymbolAddress((void**)&p_s,    g_s);
    cudaGetSymbolAddress((void**)&p_phi,  g_phi);
    cudaGetSymbolAddress((void**)&p_h1,   g_h1);
    cudaGetSymbolAddress((void**)&p_stk,  g_stk);
    cudaGetSymbolAddress((void**)&p_spl,  g_spl);
    cudaGetSymbolAddress((void**)&p_t,    g_t);

    const int SMEM_HM = 4 * 128 * HP * 2;    // 73728
    const int SMEM_RO = 4 * 128 * HP2 * 2;   // 139264
    cudaFuncSetAttribute(hmma_gemm<128, false, true,  false, false>,
                         cudaFuncAttributeMaxDynamicSharedMemorySize, SMEM_HM);
    cudaFuncSetAttribute(hmma_gemm<128, false, false, false, false>,
                         cudaFuncAttributeMaxDynamicSharedMemorySize, SMEM_HM);
    cudaFuncSetAttribute(hmma_gemm<256, false, true,  false, false>,
                         cudaFuncAttributeMaxDynamicSharedMemorySize, SMEM_HM);
    cudaFuncSetAttribute(hmma_gemm<256, true,  false, true,  false>,
                         cudaFuncAttributeMaxDynamicSharedMemorySize, SMEM_HM);
    cudaFuncSetAttribute(hmma_gemm<256, true,  false, false, true>,
                         cudaFuncAttributeMaxDynamicSharedMemorySize, SMEM_HM);
    cudaFuncSetAttribute(readout_mma,
                         cudaFuncAttributeMaxDynamicSharedMemorySize, SMEM_RO);

    const int gH = (NN + 127) / 128;  // 157
    const int gE = EE / 128;          // 2500

    init_kernel<<<2048, 256>>>(emb, z, out);
    prep_kernel<<<(EE + 255) / 256, 256>>>(xyz, nbrs);

    // CSR build
    zero_rowptr<<<(NN + 256) / 256, 256>>>();
    hist_kernel<<<(EE + 255) / 256, 256>>>(nbrs);
    scan_kernel<<<1, 1024>>>();      // also fills g_cursor
    scatter_kernel<<<(EE + 255) / 256, 256>>>(nbrs);

    for (int l = 0; l < 3; l++) {
        int sel = l & 1;
        int cur = sel ^ 1;

        // phi = swish(s @ msg_w1 + b1) @ msg_w2 + b2
        hmma_gemm<128, false, true, false, false><<<dim3(gH, 1), 256, SMEM_HM>>>(
            p_s, msg_w1 + l * 128 * 128, 128, msg_b1 + l * 128, 1.f, p_h1, nullptr, NN,
            nullptr, nullptr, nullptr, nullptr);
        hmma_gemm<128, false, false, false, false><<<dim3(gH, 3), 256, SMEM_HM>>>(
            p_h1, msg_w2 + l * 128 * 384, 384, msg_b2 + l * 384, 1.f, p_phi, nullptr, NN,
            nullptr, nullptr, nullptr, nullptr);

        // CSR message pass (smem-staged)
        msg2_kernel<<<NN, 128>>>(nbrs, msg_dw + l * RB * 384, msg_db + l * 384, sel);

        // update block
        upd1_kernel<<<(NN + TA - 1) / TA, 128>>>(upd_u + l * 128 * 128,
                                                 upd_v + l * 128 * 128, cur);
        hmma_gemm<256, false, true, false, false><<<dim3(gH, 1), 256, SMEM_HM>>>(
            p_stk, upd_w1 + l * 256 * 128, 128, upd_b1 + l * 128, 1.f, p_h1, nullptr, NN,
            nullptr, nullptr, nullptr, nullptr);
        hmma_gemm<128, false, false, false, false><<<dim3(gH, 3), 256, SMEM_HM>>>(
            p_h1, upd_w2 + l * 128 * 384, 384, upd_b2 + l * 384, 1.f, p_spl, nullptr, NN,
            nullptr, nullptr, nullptr, nullptr);
        apply_kernel<<<(NN * 128 + 255) / 256, 256>>>(cur);

        // edge MLP (factored): t per node
        hmma_gemm<128, false, false, false, false><<<dim3(gH, 2), 256, SMEM_HM>>>(
            p_s, edge_w1 + l * 128 * 256, 256, edge_b1 + l * 256, 0.5f, p_t, nullptr, NN,
            nullptr, nullptr, nullptr, nullptr);

        if (l == 0) {
            // edge2 with fused eij-init term in epilogue (write, not accumulate)
            hmma_gemm<256, true, false, false, true><<<dim3(gE, 1), 256, SMEM_HM>>>(
                p_t, edge_w2, 128, edge_b2, 1.f, p_eij, nbrs, EE,
                p_rbf, p_env, de_w, de_b);
        } else {
            hmma_gemm<256, true, false, true, false><<<dim3(gE, 1), 256, SMEM_HM>>>(
                p_t, edge_w2 + l * 256 * 128, 128, edge_b2 + l * 128, 1.f, p_eij, nbrs, EE,
                nullptr, nullptr, nullptr, nullptr);
        }
    }

    // fused HMMA readout
    readout_mma<<<gE, 256, SMEM_RO>>>(ro_w1, ro_b1, ro_w2, ro_b2, nbrs, out);

    (void)in_sizes; (void)n_in; (void)out_size;
}

// round 14
// speedup vs baseline: 1.0118x; 1.0118x over previous
#include <cuda_runtime.h>
#include <cuda_fp16.h>
#include <math.h>

// ---------------- problem constants ----------------
constexpr int NN = 20000;
constexpr int EE = 320000;
constexpr int RB = 20;    // NRBF
constexpr float PI_F = 3.14159265358979323846f;
constexpr float EPS3 = 3e-15f;

// ---------------- device scratch ----------------
__device__ float g_rbf [(size_t)EE * RB];
__device__ float g_env [EE];
__device__ float g_unit[(size_t)EE * 3];
__device__ float g_eij [(size_t)EE * 128];
__device__ float g_s   [(size_t)NN * 128];
__device__ float g_v0  [(size_t)NN * 384];
__device__ float g_v1  [(size_t)NN * 384];
__device__ float g_phi [(size_t)NN * 384];
__device__ float g_h1  [(size_t)NN * 128];
__device__ float g_uv  [(size_t)NN * 384];
__device__ float g_dot [(size_t)NN * 128];
__device__ float g_stk [(size_t)NN * 256];
__device__ float g_spl [(size_t)NN * 384];
__device__ float g_t   [(size_t)NN * 256];
// CSR by src
__device__ int g_rowptr[NN + 1];
__device__ int g_cursor[NN];
__device__ int g_perm  [EE];

__device__ __forceinline__ float swish(float x) {
    return x / (1.f + __expf(-x));
}

__device__ __forceinline__ void split_h(float x, __half& hi, __half& lo) {
    hi = __float2half_rn(x);
    lo = __float2half_rn(x - __half2float(hi));
}

__device__ __forceinline__ void hmma(float* d, const unsigned* a, const unsigned* b) {
    asm volatile(
        "mma.sync.aligned.m16n8k16.row.col.f32.f16.f16.f32 "
        "{%0,%1,%2,%3}, {%4,%5,%6,%7}, {%8,%9}, {%0,%1,%2,%3};"
        : "+f"(d[0]), "+f"(d[1]), "+f"(d[2]), "+f"(d[3])
        : "r"(a[0]), "r"(a[1]), "r"(a[2]), "r"(a[3]), "r"(b[0]), "r"(b[1]));
}

// ---------------- init ----------------
__global__ void init_kernel(const float* __restrict__ emb, const int* __restrict__ z,
                            float* __restrict__ out) {
    int stride = gridDim.x * blockDim.x;
    for (int i = blockIdx.x * blockDim.x + threadIdx.x; i < NN * 384; i += stride) {
        g_v0[i] = 0.f;
        if (i < NN * 128) {
            int n = i >> 7, f = i & 127;
            g_s[i] = emb[z[n] * 128 + f];
        }
        if (i < NN * 3) out[i] = 0.f;
    }
}

// ---------------- CSR build ----------------
__global__ void zero_rowptr() {
    int i = blockIdx.x * blockDim.x + threadIdx.x;
    if (i <= NN) g_rowptr[i] = 0;
}
__global__ void hist_kernel(const int* __restrict__ nbrs) {
    int e = blockIdx.x * blockDim.x + threadIdx.x;
    if (e < EE) atomicAdd(&g_rowptr[nbrs[2 * e] + 1], 1);
}
__global__ void scan_kernel() {
    __shared__ int sm[1024];
    __shared__ int carry;
    int t = threadIdx.x;
    if (t == 0) carry = 0;
    __syncthreads();
    int nch = (NN + 1 + 1023) / 1024;
    for (int c = 0; c < nch; c++) {
        int i = c * 1024 + t;
        int v = (i <= NN) ? g_rowptr[i] : 0;
        sm[t] = v;
        __syncthreads();
        #pragma unroll
        for (int off = 1; off < 1024; off <<= 1) {
            int x = (t >= off) ? sm[t - off] : 0;
            __syncthreads();
            sm[t] += x;
            __syncthreads();
        }
        if (i <= NN) {
            int val = sm[t] + carry;
            g_rowptr[i] = val;
            if (i < NN) g_cursor[i] = val;
        }
        int total = sm[1023];
        __syncthreads();
        if (t == 0) carry += total;
        __syncthreads();
    }
}
__global__ void scatter_kernel(const int* __restrict__ nbrs) {
    int e = blockIdx.x * blockDim.x + threadIdx.x;
    if (e < EE) {
        int pos = atomicAdd(&g_cursor[nbrs[2 * e]], 1);
        g_perm[pos] = e;
    }
}

// ---------------- per-edge geometry ----------------
__global__ void prep_kernel(const float* __restrict__ xyz, const int* __restrict__ nbrs) {
    int e = blockIdx.x * blockDim.x + threadIdx.x;
    if (e >= EE) return;
    int s = nbrs[2 * e], d = nbrs[2 * e + 1];
    float dx = xyz[d * 3 + 0] - xyz[s * 3 + 0];
    float dy = xyz[d * 3 + 1] - xyz[s * 3 + 1];
    float dz = xyz[d * 3 + 2] - xyz[s * 3 + 2];
    float d2 = dx * dx + dy * dy + dz * dz + EPS3;
    float dist = sqrtf(d2);
    float inv = 1.f / dist;
    g_unit[(size_t)e * 3 + 0] = dx * inv;
    g_unit[(size_t)e * 3 + 1] = dy * inv;
    g_unit[(size_t)e * 3 + 2] = dz * inv;
    float env = (dist < 5.f) ? 0.5f * (cosf(dist * (PI_F / 5.f)) + 1.f) : 0.f;
    g_env[e] = env;
    float base = dist * (PI_F / 5.f);
    #pragma unroll
    for (int k = 1; k <= RB; k++) {
        g_rbf[(size_t)e * RB + (k - 1)] = sinf(base * (float)k) * inv;
    }
}

// ================ generic HMMA GEMM (R12 path) ================
// RBF0: epilogue adds (rbf@de_w + de_b)*env (the e_ij init term) instead of ACCUM.
constexpr int HP = 72;
template<int K, bool GATHER_SWISH, bool SWISH_OUT, bool ACCUM, bool RBF0>
__global__ void __launch_bounds__(256, 2)
hmma_gemm(const float* __restrict__ Ain, const float* __restrict__ W, int ldw,
          const float* __restrict__ bias, float bias_scale, float* __restrict__ C,
          const int* __restrict__ nbrs, int M,
          const float* __restrict__ rbfp, const float* __restrict__ envp,
          const float* __restrict__ dew,  const float* __restrict__ deb) {
    extern __shared__ __align__(16) __half hsm[];
    __half* Ah = hsm;
    __half* Al = Ah + 128 * HP;
    __half* Bh = Al + 128 * HP;
    __half* Bl = Bh + 128 * HP;
    __shared__ int s_src[128], s_dst[128];
    __shared__ __align__(16) float s_dew [RBF0 ? RB * 128 : 1];
    __shared__ __align__(16) float s_rbfv[RBF0 ? 128 * RB : 1];
    __shared__ float s_envv[RBF0 ? 128 : 1];
    __shared__ float s_deb [RBF0 ? 128 : 1];

    int tid = threadIdx.x;
    int wid = tid >> 5, lane = tid & 31;
    int g = lane >> 2, tq = lane & 3;
    int wm0 = (wid & 3) * 32;
    int n0w = (wid >> 2) * 64;
    int m0b = blockIdx.x * 128;
    int col0 = blockIdx.y * 128;

    if (GATHER_SWISH && tid < 128) {
        int m = m0b + tid;
        s_src[tid] = (m < M) ? nbrs[2 * m] : 0;
        s_dst[tid] = (m < M) ? nbrs[2 * m + 1] : 0;
    }
    if (RBF0) {
        for (int i = tid; i < RB * 128; i += 256) s_dew[i] = dew[i];
        for (int idx = tid; idx < 128 * 5; idx += 256) {
            int r = idx / 5, q = idx - r * 5;
            ((float4*)&s_rbfv[r * RB])[q] =
                ((const float4*)&rbfp[(size_t)(m0b + r) * RB])[q];
        }
        if (tid < 128) {
            s_envv[tid] = envp[m0b + tid];
            s_deb[tid]  = deb[tid];
        }
    }

    float acc[2][8][4];
    #pragma unroll
    for (int mi = 0; mi < 2; mi++)
        #pragma unroll
        for (int ni = 0; ni < 8; ni++)
            #pragma unroll
            for (int j = 0; j < 4; j++) acc[mi][ni][j] = 0.f;

    constexpr int NCH = K / 64;
    for (int kc = 0; kc < NCH; kc++) {
        __syncthreads();
        for (int idx = tid; idx < 128 * 16; idx += 256) {
            int r = idx >> 4, k = (idx & 15) * 4;
            int m = m0b + r;
            float x[4] = {0.f, 0.f, 0.f, 0.f};
            if (m < M) {
                if (GATHER_SWISH) {
                    float4 a = *(const float4*)&Ain[(size_t)s_src[r] * K + kc * 64 + k];
                    float4 b = *(const float4*)&Ain[(size_t)s_dst[r] * K + kc * 64 + k];
                    x[0] = swish(a.x + b.x); x[1] = swish(a.y + b.y);
                    x[2] = swish(a.z + b.z); x[3] = swish(a.w + b.w);
                } else {
                    float4 a = *(const float4*)&Ain[(size_t)m * K + kc * 64 + k];
                    x[0] = a.x; x[1] = a.y; x[2] = a.z; x[3] = a.w;
                }
            }
            #pragma unroll
            for (int j = 0; j < 4; j++) {
                __half hi, lo;
                split_h(x[j], hi, lo);
                Ah[r * HP + k + j] = hi;
                Al[r * HP + k + j] = lo;
            }
        }
        for (int idx = tid; idx < 128 * 16; idx += 256) {
            int n = idx & 127, kl = (idx >> 7) * 4;
            #pragma unroll
            for (int j = 0; j < 4; j++) {
                float w = W[(size_t)(kc * 64 + kl + j) * ldw + col0 + n];
                __half hi, lo;
                split_h(w, hi, lo);
                Bh[n * HP + kl + j] = hi;
                Bl[n * HP + kl + j] = lo;
            }
        }
        __syncthreads();

        #pragma unroll
        for (int ks = 0; ks < 4; ks++) {
            int kl = ks * 16;
            unsigned ah[2][4], al[2][4];
            #pragma unroll
            for (int mi = 0; mi < 2; mi++) {
                int r = wm0 + mi * 16;
                ah[mi][0] = *(const unsigned*)&Ah[(r + g) * HP + kl + 2 * tq];
                ah[mi][1] = *(const unsigned*)&Ah[(r + g + 8) * HP + kl + 2 * tq];
                ah[mi][2] = *(const unsigned*)&Ah[(r + g) * HP + kl + 8 + 2 * tq];
                ah[mi][3] = *(const unsigned*)&Ah[(r + g + 8) * HP + kl + 8 + 2 * tq];
                al[mi][0] = *(const unsigned*)&Al[(r + g) * HP + kl + 2 * tq];
                al[mi][1] = *(const unsigned*)&Al[(r + g + 8) * HP + kl + 2 * tq];
                al[mi][2] = *(const unsigned*)&Al[(r + g) * HP + kl + 8 + 2 * tq];
                al[mi][3] = *(const unsigned*)&Al[(r + g + 8) * HP + kl + 8 + 2 * tq];
            }
            #pragma unroll
            for (int ni = 0; ni < 8; ni++) {
                int n = n0w + ni * 8 + g;
                unsigned bh[2], bl[2];
                bh[0] = *(const unsigned*)&Bh[n * HP + kl + 2 * tq];
                bh[1] = *(const unsigned*)&Bh[n * HP + kl + 8 + 2 * tq];
                bl[0] = *(const unsigned*)&Bl[n * HP + kl + 2 * tq];
                bl[1] = *(const unsigned*)&Bl[n * HP + kl + 8 + 2 * tq];
                #pragma unroll
                for (int mi = 0; mi < 2; mi++) {
                    hmma(acc[mi][ni], ah[mi], bh);
                    hmma(acc[mi][ni], ah[mi], bl);
                    hmma(acc[mi][ni], al[mi], bh);
                }
            }
        }
    }

    #pragma unroll
    for (int mi = 0; mi < 2; mi++) {
        #pragma unroll
        for (int ni = 0; ni < 8; ni++) {
            int col = n0w + ni * 8 + 2 * tq;
            float2 bb = *(const float2*)&bias[col0 + col];
            bb.x *= bias_scale; bb.y *= bias_scale;
            #pragma unroll
            for (int h = 0; h < 2; h++) {
                int r = wm0 + mi * 16 + g + h * 8;
                int m = m0b + r;
                if (m >= M) continue;
                float2 o;
                o.x = acc[mi][ni][2 * h + 0] + bb.x;
                o.y = acc[mi][ni][2 * h + 1] + bb.y;
                if (SWISH_OUT) { o.x = swish(o.x); o.y = swish(o.y); }
                size_t ci = (size_t)m * ldw + col0 + col;
                if (RBF0) {
                    float dx = s_deb[col], dy = s_deb[col + 1];
                    const float* rrow = &s_rbfv[r * RB];
                    #pragma unroll
                    for (int k = 0; k < RB; k++) {
                        float rv = rrow[k];
                        dx = fmaf(rv, s_dew[k * 128 + col],     dx);
                        dy = fmaf(rv, s_dew[k * 128 + col + 1], dy);
                    }
                    float ev = s_envv[r];
                    o.x += ev * dx;
                    o.y += ev * dy;
                } else if (ACCUM) {
                    float2 old = *(const float2*)&C[ci];
                    o.x += old.x; o.y += old.y;
                }
                *(float2*)&C[ci] = o;
            }
        }
    }
}

// ---------------- CSR message pass: smem-staged edge metadata ----------------
constexpr int ETILE = 32;
__global__ void __launch_bounds__(128)
msg2_kernel(const int* __restrict__ nbrs, const float* __restrict__ dw,
            const float* __restrict__ db, int sel) {
    __shared__ int   s_dst[ETILE];
    __shared__ float s_env[ETILE];
    __shared__ float s_unit[ETILE][4];
    __shared__ __align__(16) float s_rbf[ETILE][RB];

    int n = blockIdx.x;
    int t = threadIdx.x;

    float dwr0[RB], dwr1[RB], dwr2[RB];
    #pragma unroll
    for (int k = 0; k < RB; k++) {
        dwr0[k] = dw[k * 384 + t];
        dwr1[k] = dw[k * 384 + t + 128];
        dwr2[k] = dw[k * 384 + t + 256];
    }
    float db0 = db[t], db1 = db[t + 128], db2 = db[t + 256];

    const float* vold = sel ? g_v1 : g_v0;
    float*       vnew = sel ? g_v0 : g_v1;

    int start = g_rowptr[n], end = g_rowptr[n + 1];
    float accs = 0.f, av0 = 0.f, av1 = 0.f, av2 = 0.f;

    for (int tile = start; tile < end; tile += ETILE) {
        int m = min(ETILE, end - tile);
        __syncthreads();
        if (t < m) {
            int e = g_perm[tile + t];
            s_dst[t] = nbrs[2 * e + 1];
            s_env[t] = g_env[e];
            s_unit[t][0] = g_unit[(size_t)e * 3 + 0];
            s_unit[t][1] = g_unit[(size_t)e * 3 + 1];
            s_unit[t][2] = g_unit[(size_t)e * 3 + 2];
        }
        for (int idx = t; idx < m * 5; idx += 128) {
            int le = idx / 5, q = idx - le * 5;
            int e = g_perm[tile + le];
            ((float4*)s_rbf[le])[q] = ((const float4*)&g_rbf[(size_t)e * RB])[q];
        }
        __syncthreads();

        for (int le = 0; le < m; le++) {
            const float4* rb4 = (const float4*)s_rbf[le];
            float4 r0 = rb4[0], r1 = rb4[1], r2 = rb4[2], r3 = rb4[3], r4 = rb4[4];
            float rb[RB] = {r0.x, r0.y, r0.z, r0.w, r1.x, r1.y, r1.z, r1.w,
                            r2.x, r2.y, r2.z, r2.w, r3.x, r3.y, r3.z, r3.w,
                            r4.x, r4.y, r4.z, r4.w};
            float a0 = db0, a1 = db1, a2 = db2;
            #pragma unroll
            for (int k = 0; k < RB; k++) {
                a0 = fmaf(rb[k], dwr0[k], a0);
                a1 = fmaf(rb[k], dwr1[k], a1);
                a2 = fmaf(rb[k], dwr2[k], a2);
            }
            float env = s_env[le];
            a0 *= env; a1 *= env; a2 *= env;

            int dst = s_dst[le];
            const float* ph = g_phi + (size_t)dst * 384;
            float s0 = ph[t] * a0;
            float s1 = ph[t + 128] * a1;
            float s2 = ph[t + 256] * a2;
            accs += s1;

            const float* vo = vold + (size_t)dst * 384 + 3 * t;
            av0 += fmaf(s0, vo[0], s2 * s_unit[le][0]);
            av1 += fmaf(s0, vo[1], s2 * s_unit[le][1]);
            av2 += fmaf(s0, vo[2], s2 * s_unit[le][2]);
        }
    }

    g_s[(size_t)n * 128 + t] += accs;
    const float* vs = vold + (size_t)n * 384 + 3 * t;
    float*       vp = vnew + (size_t)n * 384 + 3 * t;
    vp[0] = vs[0] + av0;
    vp[1] = vs[1] + av1;
    vp[2] = vs[2] + av2;
}

// ---------------- update stage 1 ----------------
constexpr int TA = 8;
__global__ void __launch_bounds__(128)
upd1_kernel(const float* __restrict__ U, const float* __restrict__ Vw, int sel) {
    __shared__ __align__(16) float v_s[TA * 384];
    int t = threadIdx.x;
    int n0 = blockIdx.x * TA;
    const float* vcur = sel ? g_v1 : g_v0;

    for (int i = t; i < TA * 384; i += 128) {
        size_t gi = (size_t)n0 * 384 + i;
        v_s[i] = (gi < (size_t)NN * 384) ? vcur[gi] : 0.f;
    }
    __syncthreads();

    float uv[TA][3], vv[TA][3];
    #pragma unroll
    for (int a = 0; a < TA; a++)
        #pragma unroll
        for (int d = 0; d < 3; d++) { uv[a][d] = 0.f; vv[a][d] = 0.f; }

    for (int f4 = 0; f4 < 32; f4++) {
        float u0 = U[(f4 * 4 + 0) * 128 + t];
        float u1 = U[(f4 * 4 + 1) * 128 + t];
        float u2 = U[(f4 * 4 + 2) * 128 + t];
        float u3 = U[(f4 * 4 + 3) * 128 + t];
        float w0 = Vw[(f4 * 4 + 0) * 128 + t];
        float w1 = Vw[(f4 * 4 + 1) * 128 + t];
        float w2 = Vw[(f4 * 4 + 2) * 128 + t];
        float w3 = Vw[(f4 * 4 + 3) * 128 + t];
        #pragma unroll
        for (int a = 0; a < TA; a++) {
            const float4* vp = reinterpret_cast<const float4*>(&v_s[a * 384 + f4 * 12]);
            float4 p0 = vp[0], p1 = vp[1], p2 = vp[2];
            uv[a][0] = fmaf(p0.x, u0, fmaf(p0.w, u1, fmaf(p1.z, u2, fmaf(p2.y, u3, uv[a][0]))));
            uv[a][1] = fmaf(p0.y, u0, fmaf(p1.x, u1, fmaf(p1.w, u2, fmaf(p2.z, u3, uv[a][1]))));
            uv[a][2] = fmaf(p0.z, u0, fmaf(p1.y, u1, fmaf(p2.x, u2, fmaf(p2.w, u3, uv[a][2]))));
            vv[a][0] = fmaf(p0.x, w0, fmaf(p0.w, w1, fmaf(p1.z, w2, fmaf(p2.y, w3, vv[a][0]))));
            vv[a][1] = fmaf(p0.y, w0, fmaf(p1.x, w1, fmaf(p1.w, w2, fmaf(p2.z, w3, vv[a][1]))));
            vv[a][2] = fmaf(p0.z, w0, fmaf(p1.y, w1, fmaf(p2.x, w2, fmaf(p2.w, w3, vv[a][2]))));
        }
    }

    #pragma unroll
    for (int a = 0; a < TA; a++) {
        int n = n0 + a;
        if (n >= NN) break;
        float dt = uv[a][0] * vv[a][0] + uv[a][1] * vv[a][1] + uv[a][2] * vv[a][2];
        float vn = sqrtf(vv[a][0] * vv[a][0] + vv[a][1] * vv[a][1] + vv[a][2] * vv[a][2] + EPS3);
        g_uv[(size_t)n * 384 + 3 * t + 0] = uv[a][0];
        g_uv[(size_t)n * 384 + 3 * t + 1] = uv[a][1];
        g_uv[(size_t)n * 384 + 3 * t + 2] = uv[a][2];
        g_dot[(size_t)n * 128 + t] = dt;
        g_stk[(size_t)n * 256 + t] = g_s[(size_t)n * 128 + t];
        g_stk[(size_t)n * 256 + 128 + t] = vn;
    }
}

// ---------------- update apply ----------------
__global__ void apply_kernel(int sel) {
    int i = blockIdx.x * blockDim.x + threadIdx.x;
    if (i >= NN * 128) return;
    int n = i >> 7, g = i & 127;
    float avv = g_spl[(size_t)n * 384 + g];
    float asv = g_spl[(size_t)n * 384 + 128 + g];
    float ass = g_spl[(size_t)n * 384 + 256 + g];
    float* v = (sel ? g_v1 : g_v0) + (size_t)n * 384 + 3 * g;
    const float* uv = g_uv + (size_t)n * 384 + 3 * g;
    v[0] += uv[0] * avv;
    v[1] += uv[1] * avv;
    v[2] += uv[2] * avv;
    g_s[i] += g_dot[i] * asv + ass;
}

// ================ HMMA fused readout (R12 path) ================
constexpr int HP2 = 136;
__global__ void __launch_bounds__(256)
readout_mma(const float* __restrict__ W1, const float* __restrict__ b1,
            const float* __restrict__ w2, const float* __restrict__ b2,
            const int* __restrict__ nbrs, float* __restrict__ out) {
    extern __shared__ __align__(16) __half hsm[];
    __half* Ah = hsm;
    __half* Al = Ah + 128 * HP2;
    __half* Bh = Al + 128 * HP2;
    __half* Bl = Bh + 128 * HP2;
    __shared__ float red[128][2];

    int tid = threadIdx.x;
    int wid = tid >> 5, lane = tid & 31;
    int g = lane >> 2, tq = lane & 3;
    int m0 = (wid & 3) * 32;
    int n0w = (wid >> 2) * 64;
    int nw = wid >> 2;
    int e0 = blockIdx.x * 128;

    for (int idx = tid; idx < 128 * 32; idx += 256) {
        int e = idx >> 5, k = (idx & 31) * 4;
        float4 a = *(const float4*)&g_eij[(size_t)(e0 + e) * 128 + k];
        float x[4] = {a.x, a.y, a.z, a.w};
        #pragma unroll
        for (int j = 0; j < 4; j++) {
            __half hi, lo;
            split_h(x[j], hi, lo);
            Ah[e * HP2 + k + j] = hi;
            Al[e * HP2 + k + j] = lo;
        }
    }

    float rs[2][2] = {{0.f, 0.f}, {0.f, 0.f}};

    for (int nc = 0; nc < 2; nc++) {
        __syncthreads();
        for (int idx = tid; idx < 128 * 32; idx += 256) {
            int n = idx & 127, k = (idx >> 7) * 4;
            #pragma unroll
            for (int j = 0; j < 4; j++) {
                float w = W1[(size_t)(k + j) * 256 + nc * 128 + n];
                __half hi, lo;
                split_h(w, hi, lo);
                Bh[n * HP2 + k + j] = hi;
                Bl[n * HP2 + k + j] = lo;
            }
        }
        __syncthreads();

        float acc[2][8][4];
        #pragma unroll
        for (int mi = 0; mi < 2; mi++)
            #pragma unroll
            for (int ni = 0; ni < 8; ni++)
                #pragma unroll
                for (int j = 0; j < 4; j++) acc[mi][ni][j] = 0.f;

        #pragma unroll
        for (int ks = 0; ks < 8; ks++) {
            int kl = ks * 16;
            unsigned ah[2][4], al[2][4];
            #pragma unroll
            for (int mi = 0; mi < 2; mi++) {
                int r = m0 + mi * 16;
                ah[mi][0] = *(const unsigned*)&Ah[(r + g) * HP2 + kl + 2 * tq];
                ah[mi][1] = *(const unsigned*)&Ah[(r + g + 8) * HP2 + kl + 2 * tq];
                ah[mi][2] = *(const unsigned*)&Ah[(r + g) * HP2 + kl + 8 + 2 * tq];
                ah[mi][3] = *(const unsigned*)&Ah[(r + g + 8) * HP2 + kl + 8 + 2 * tq];
                al[mi][0] = *(const unsigned*)&Al[(r + g) * HP2 + kl + 2 * tq];
                al[mi][1] = *(const unsigned*)&Al[(r + g + 8) * HP2 + kl + 2 * tq];
                al[mi][2] = *(const unsigned*)&Al[(r + g) * HP2 + kl + 8 + 2 * tq];
                al[mi][3] = *(const unsigned*)&Al[(r + g + 8) * HP2 + kl + 8 + 2 * tq];
            }
            #pragma unroll
            for (int ni = 0; ni < 8; ni++) {
                int n = n0w + ni * 8 + g;
                unsigned bh[2], bl[2];
                bh[0] = *(const unsigned*)&Bh[n * HP2 + kl + 2 * tq];
                bh[1] = *(const unsigned*)&Bh[n * HP2 + kl + 8 + 2 * tq];
                bl[0] = *(const unsigned*)&Bl[n * HP2 + kl + 2 * tq];
                bl[1] = *(const unsigned*)&Bl[n * HP2 + kl + 8 + 2 * tq];
                #pragma unroll
                for (int mi = 0; mi < 2; mi++) {
                    hmma(acc[mi][ni], ah[mi], bh);
                    hmma(acc[mi][ni], ah[mi], bl);
                    hmma(acc[mi][ni], al[mi], bh);
                }
            }
        }

        #pragma unroll
        for (int mi = 0; mi < 2; mi++) {
            #pragma unroll
            for (int ni = 0; ni < 8; ni++) {
                int c = nc * 128 + n0w + ni * 8 + 2 * tq;
                float2 bb = *(const float2*)&b1[c];
                float2 ww = *(const float2*)&w2[c];
                rs[mi][0] += swish(acc[mi][ni][0] + bb.x) * ww.x
                           + swish(acc[mi][ni][1] + bb.y) * ww.y;
                rs[mi][1] += swish(acc[mi][ni][2] + bb.x) * ww.x
                           + swish(acc[mi][ni][3] + bb.y) * ww.y;
            }
        }
    }

    #pragma unroll
    for (int mi = 0; mi < 2; mi++) {
        #pragma unroll
        for (int h = 0; h < 2; h++) {
            float v = rs[mi][h];
            v += __shfl_xor_sync(0xffffffff, v, 1);
            v += __shfl_xor_sync(0xffffffff, v, 2);
            rs[mi][h] = v;
        }
    }
    if (tq == 0) {
        red[m0 + g][nw]          = rs[0][0];
        red[m0 + g + 8][nw]      = rs[0][1];
        red[m0 + 16 + g][nw]     = rs[1][0];
        red[m0 + 16 + g + 8][nw] = rs[1][1];
    }
    __syncthreads();

    if (tid < 128) {
        int e = e0 + tid;
        float s = red[tid][0] + red[tid][1] + b2[0];
        int src = nbrs[2 * e], dst = nbrs[2 * e + 1];
        float fx = s * g_unit[(size_t)e * 3 + 0];
        float fy = s * g_unit[(size_t)e * 3 + 1];
        float fz = s * g_unit[(size_t)e * 3 + 2];
        atomicAdd(&out[src * 3 + 0], fx);
        atomicAdd(&out[src * 3 + 1], fy);
        atomicAdd(&out[src * 3 + 2], fz);
        atomicAdd(&out[dst * 3 + 0], -fx);
        atomicAdd(&out[dst * 3 + 1], -fy);
        atomicAdd(&out[dst * 3 + 2], -fz);
    }
}

// ---------------- host launcher ----------------
extern "C" void kernel_launch(void* const* d_in, const int* in_sizes, int n_in,
                              void* d_out, int out_size) {
    const float* xyz     = (const float*)d_in[0];
    const int*   z       = (const int*)  d_in[1];
    const int*   nbrs    = (const int*)  d_in[2];
    const float* emb     = (const float*)d_in[3];
    const float* de_w    = (const float*)d_in[4];
    const float* de_b    = (const float*)d_in[5];
    const float* msg_w1  = (const float*)d_in[6];
    const float* msg_b1  = (const float*)d_in[7];
    const float* msg_w2  = (const float*)d_in[8];
    const float* msg_b2  = (const float*)d_in[9];
    const float* msg_dw  = (const float*)d_in[10];
    const float* msg_db  = (const float*)d_in[11];
    const float* upd_u   = (const float*)d_in[12];
    const float* upd_v   = (const float*)d_in[13];
    const float* upd_w1  = (const float*)d_in[14];
    const float* upd_b1  = (const float*)d_in[15];
    const float* upd_w2  = (const float*)d_in[16];
    const float* upd_b2  = (const float*)d_in[17];
    const float* edge_w1 = (const float*)d_in[18];
    const float* edge_b1 = (const float*)d_in[19];
    const float* edge_w2 = (const float*)d_in[20];
    const float* edge_b2 = (const float*)d_in[21];
    const float* ro_w1   = (const float*)d_in[22];
    const float* ro_b1   = (const float*)d_in[23];
    const float* ro_w2   = (const float*)d_in[24];
    const float* ro_b2   = (const float*)d_in[25];
    float* out = (float*)d_out;

    float *p_rbf, *p_env, *p_eij, *p_s, *p_phi, *p_h1, *p_stk, *p_spl, *p_t;
    cudaGetSymbolAddress((void**)&p_rbf,  g_rbf);
    cudaGetSymbolAddress((void**)&p_env,  g_env);
    cudaGetSymbolAddress((void**)&p_eij,  g_eij);
    cudaGetSymbolAddress((void**)&p_s,    g_s);
    cudaGetSymbolAddress((void**)&p_phi,  g_phi);
    cudaGetSymbolAddress((void**)&p_h1,   g_h1);
    cudaGetSymbolAddress((void**)&p_stk,  g_stk);
    cudaGetSymbolAddress((void**)&p_spl,  g_spl);
    cudaGetSymbolAddress((void**)&p_t,    g_t);

    const int SMEM_HM = 4 * 128 * HP * 2;    // 73728
    const int SMEM_RO = 4 * 128 * HP2 * 2;   // 139264
    cudaFuncSetAttribute(hmma_gemm<128, false, true,  false, false>,
                         cudaFuncAttributeMaxDynamicSharedMemorySize, SMEM_HM);
    cudaFuncSetAttribute(hmma_gemm<128, false, false, false, false>,
                         cudaFuncAttributeMaxDynamicSharedMemorySize, SMEM_HM);
    cudaFuncSetAttribute(hmma_gemm<256, false, true,  false, false>,
                         cudaFuncAttributeMaxDynamicSharedMemorySize, SMEM_HM);
    cudaFuncSetAttribute(hmma_gemm<256, true,  false, true,  false>,
                         cudaFuncAttributeMaxDynamicSharedMemorySize, SMEM_HM);
    cudaFuncSetAttribute(hmma_gemm<256, true,  false, false, true>,
                         cudaFuncAttributeMaxDynamicSharedMemorySize, SMEM_HM);
    cudaFuncSetAttribute(readout_mma,
                         cudaFuncAttributeMaxDynamicSharedMemorySize, SMEM_RO);

    const int gH = (NN + 127) / 128;  // 157
    const int gE = EE / 128;          // 2500

    init_kernel<<<2048, 256>>>(emb, z, out);
    prep_kernel<<<(EE + 255) / 256, 256>>>(xyz, nbrs);

    // CSR build
    zero_rowptr<<<(NN + 256) / 256, 256>>>();
    hist_kernel<<<(EE + 255) / 256, 256>>>(nbrs);
    scan_kernel<<<1, 1024>>>();      // also fills g_cursor
    scatter_kernel<<<(EE + 255) / 256, 256>>>(nbrs);

    for (int l = 0; l < 3; l++) {
        int sel = l & 1;
        int cur = sel ^ 1;

        // phi = swish(s @ msg_w1 + b1) @ msg_w2 + b2
        hmma_gemm<128, false, true, false, false><<<dim3(gH, 1), 256, SMEM_HM>>>(
            p_s, msg_w1 + l * 128 * 128, 128, msg_b1 + l * 128, 1.f, p_h1, nullptr, NN,
            nullptr, nullptr, nullptr, nullptr);
        hmma_gemm<128, false, false, false, false><<<dim3(gH, 3), 256, SMEM_HM>>>(
            p_h1, msg_w2 + l * 128 * 384, 384, msg_b2 + l * 384, 1.f, p_phi, nullptr, NN,
            nullptr, nullptr, nullptr, nullptr);

        // CSR message pass (smem-staged)
        msg2_kernel<<<NN, 128>>>(nbrs, msg_dw + l * RB * 384, msg_db + l * 384, sel);

        // update block
        upd1_kernel<<<(NN + TA - 1) / TA, 128>>>(upd_u + l * 128 * 128,
                                                 upd_v + l * 128 * 128, cur);
        hmma_gemm<256, false, true, false, false><<<dim3(gH, 1), 256, SMEM_HM>>>(
            p_stk, upd_w1 + l * 256 * 128, 128, upd_b1 + l * 128, 1.f, p_h1, nullptr, NN,
            nullptr, nullptr, nullptr, nullptr);
        hmma_gemm<128, false, false, false, false><<<dim3(gH, 3), 256, SMEM_HM>>>(
            p_h1, upd_w2 + l * 128 * 384, 384, upd_b2 + l * 384, 1.f, p_spl, nullptr, NN,
            nullptr, nullptr, nullptr, nullptr);
        apply_kernel<<<(NN * 128 + 255) / 256, 256>>>(cur);

        // edge MLP (factored): t per node
        hmma_gemm<128, false, false, false, false><<<dim3(gH, 2), 256, SMEM_HM>>>(
            p_s, edge_w1 + l * 128 * 256, 256, edge_b1 + l * 256, 0.5f, p_t, nullptr, NN,
            nullptr, nullptr, nullptr, nullptr);

        if (l == 0) {
            // edge2 with fused eij-init term in epilogue (write, not accumulate)
            hmma_gemm<256, true, false, false, true><<<dim3(gE, 1), 256, SMEM_HM>>>(
                p_t, edge_w2, 128, edge_b2, 1.f, p_eij, nbrs, EE,
                p_rbf, p_env, de_w, de_b);
        } else {
            hmma_gemm<256, true, false, true, false><<<dim3(gE, 1), 256, SMEM_HM>>>(
                p_t, edge_w2 + l * 256 * 128, 128, edge_b2 + l * 128, 1.f, p_eij, nbrs, EE,
                nullptr, nullptr, nullptr, nullptr);
        }
    }

    // fused HMMA readout
    readout_mma<<<gE, 256, SMEM_RO>>>(ro_w1, ro_b1, ro_w2, ro_b2, nbrs, out);

    (void)in_sizes; (void)n_in; (void)out_size;
}

// round 15
// speedup vs baseline: 1.0157x; 1.0038x over previous
#include <cuda_runtime.h>
#include <cuda_fp16.h>
#include <math.h>

// ---------------- problem constants ----------------
constexpr int NN = 20000;
constexpr int EE = 320000;
constexpr int RB = 20;    // NRBF
constexpr float PI_F = 3.14159265358979323846f;
constexpr float EPS3 = 3e-15f;

// ---------------- device scratch ----------------
__device__ float g_rbf [(size_t)EE * RB];
__device__ float g_env [EE];
__device__ float g_unit[(size_t)EE * 3];
__device__ float g_eij [(size_t)EE * 128];
__device__ float g_s   [(size_t)NN * 128];
__device__ float g_v0  [(size_t)NN * 384];
__device__ float g_v1  [(size_t)NN * 384];
__device__ float g_phi [(size_t)NN * 384];
__device__ float g_h1  [(size_t)NN * 128];
__device__ float g_uv  [(size_t)NN * 384];
__device__ float g_dot [(size_t)NN * 128];
__device__ float g_stk [(size_t)NN * 256];
__device__ float g_spl [(size_t)NN * 384];
__device__ float g_t   [(size_t)NN * 256];
// CSR by src
__device__ int g_rowptr[NN + 1];
__device__ int g_cursor[NN];
__device__ int g_perm  [EE];

__device__ __forceinline__ float swish(float x) {
    return x / (1.f + __expf(-x));
}

__device__ __forceinline__ void split_h(float x, __half& hi, __half& lo) {
    hi = __float2half_rn(x);
    lo = __float2half_rn(x - __half2float(hi));
}

__device__ __forceinline__ void hmma(float* d, const unsigned* a, const unsigned* b) {
    asm volatile(
        "mma.sync.aligned.m16n8k16.row.col.f32.f16.f16.f32 "
        "{%0,%1,%2,%3}, {%4,%5,%6,%7}, {%8,%9}, {%0,%1,%2,%3};"
        : "+f"(d[0]), "+f"(d[1]), "+f"(d[2]), "+f"(d[3])
        : "r"(a[0]), "r"(a[1]), "r"(a[2]), "r"(a[3]), "r"(b[0]), "r"(b[1]));
}

// ---------------- init ----------------
__global__ void init_kernel(const float* __restrict__ emb, const int* __restrict__ z,
                            float* __restrict__ out) {
    int stride = gridDim.x * blockDim.x;
    for (int i = blockIdx.x * blockDim.x + threadIdx.x; i < NN * 384; i += stride) {
        g_v0[i] = 0.f;
        if (i < NN * 128) {
            int n = i >> 7, f = i & 127;
            g_s[i] = emb[z[n] * 128 + f];
        }
        if (i < NN * 3) out[i] = 0.f;
    }
}

// ---------------- CSR build ----------------
__global__ void zero_rowptr() {
    int i = blockIdx.x * blockDim.x + threadIdx.x;
    if (i <= NN) g_rowptr[i] = 0;
}
__global__ void hist_kernel(const int* __restrict__ nbrs) {
    int e = blockIdx.x * blockDim.x + threadIdx.x;
    if (e < EE) atomicAdd(&g_rowptr[nbrs[2 * e] + 1], 1);
}
__global__ void scan_kernel() {
    __shared__ int sm[1024];
    __shared__ int carry;
    int t = threadIdx.x;
    if (t == 0) carry = 0;
    __syncthreads();
    int nch = (NN + 1 + 1023) / 1024;
    for (int c = 0; c < nch; c++) {
        int i = c * 1024 + t;
        int v = (i <= NN) ? g_rowptr[i] : 0;
        sm[t] = v;
        __syncthreads();
        #pragma unroll
        for (int off = 1; off < 1024; off <<= 1) {
            int x = (t >= off) ? sm[t - off] : 0;
            __syncthreads();
            sm[t] += x;
            __syncthreads();
        }
        if (i <= NN) {
            int val = sm[t] + carry;
            g_rowptr[i] = val;
            if (i < NN) g_cursor[i] = val;
        }
        int total = sm[1023];
        __syncthreads();
        if (t == 0) carry += total;
        __syncthreads();
    }
}
__global__ void scatter_kernel(const int* __restrict__ nbrs) {
    int e = blockIdx.x * blockDim.x + threadIdx.x;
    if (e < EE) {
        int pos = atomicAdd(&g_cursor[nbrs[2 * e]], 1);
        g_perm[pos] = e;
    }
}

// ---------------- per-edge geometry ----------------
__global__ void prep_kernel(const float* __restrict__ xyz, const int* __restrict__ nbrs) {
    int e = blockIdx.x * blockDim.x + threadIdx.x;
    if (e >= EE) return;
    int s = nbrs[2 * e], d = nbrs[2 * e + 1];
    float dx = xyz[d * 3 + 0] - xyz[s * 3 + 0];
    float dy = xyz[d * 3 + 1] - xyz[s * 3 + 1];
    float dz = xyz[d * 3 + 2] - xyz[s * 3 + 2];
    float d2 = dx * dx + dy * dy + dz * dz + EPS3;
    float dist = sqrtf(d2);
    float inv = 1.f / dist;
    g_unit[(size_t)e * 3 + 0] = dx * inv;
    g_unit[(size_t)e * 3 + 1] = dy * inv;
    g_unit[(size_t)e * 3 + 2] = dz * inv;
    float env = (dist < 5.f) ? 0.5f * (cosf(dist * (PI_F / 5.f)) + 1.f) : 0.f;
    g_env[e] = env;
    float base = dist * (PI_F / 5.f);
    #pragma unroll
    for (int k = 1; k <= RB; k++) {
        g_rbf[(size_t)e * RB + (k - 1)] = sinf(base * (float)k) * inv;
    }
}

// ================ generic HMMA GEMM ================
// MT: rows per block (128 or 64). RBF0 valid only with MT=128.
constexpr int HP = 72;
template<int MT, int K, bool GATHER_SWISH, bool SWISH_OUT, bool ACCUM, bool RBF0>
__global__ void __launch_bounds__(256, MT == 128 ? 2 : 3)
hmma_gemm(const float* __restrict__ Ain, const float* __restrict__ W, int ldw,
          const float* __restrict__ bias, float bias_scale, float* __restrict__ C,
          const int* __restrict__ nbrs, int M,
          const float* __restrict__ rbfp, const float* __restrict__ envp,
          const float* __restrict__ dew,  const float* __restrict__ deb) {
    extern __shared__ __align__(16) __half hsm[];
    __half* Ah = hsm;
    __half* Al = Ah + MT * HP;
    __half* Bh = Al + MT * HP;
    __half* Bl = Bh + 128 * HP;
    __shared__ int s_src[128], s_dst[128];
    __shared__ __align__(16) float s_dew [RBF0 ? RB * 128 : 1];
    __shared__ __align__(16) float s_rbfv[RBF0 ? 128 * RB : 1];
    __shared__ float s_envv[RBF0 ? 128 : 1];
    __shared__ float s_deb [RBF0 ? 128 : 1];

    constexpr int MW = (MT == 128) ? 4 : 2;   // m-warp groups
    constexpr int NI = (MT == 128) ? 8 : 4;   // 8-col groups per warp

    int tid = threadIdx.x;
    int wid = tid >> 5, lane = tid & 31;
    int g = lane >> 2, tq = lane & 3;
    int wm0 = (wid % MW) * 32;
    int n0w = (wid / MW) * (NI * 8);
    int m0b = blockIdx.x * MT;
    int col0 = blockIdx.y * 128;

    if (GATHER_SWISH && tid < MT) {
        int m = m0b + tid;
        s_src[tid] = (m < M) ? nbrs[2 * m] : 0;
        s_dst[tid] = (m < M) ? nbrs[2 * m + 1] : 0;
    }
    if (RBF0) {
        for (int i = tid; i < RB * 128; i += 256) s_dew[i] = dew[i];
        for (int idx = tid; idx < 128 * 5; idx += 256) {
            int r = idx / 5, q = idx - r * 5;
            ((float4*)&s_rbfv[r * RB])[q] =
                ((const float4*)&rbfp[(size_t)(m0b + r) * RB])[q];
        }
        if (tid < 128) {
            s_envv[tid] = envp[m0b + tid];
            s_deb[tid]  = deb[tid];
        }
    }

    float acc[2][NI][4];
    #pragma unroll
    for (int mi = 0; mi < 2; mi++)
        #pragma unroll
        for (int ni = 0; ni < NI; ni++)
            #pragma unroll
            for (int j = 0; j < 4; j++) acc[mi][ni][j] = 0.f;

    constexpr int NCH = K / 64;
    for (int kc = 0; kc < NCH; kc++) {
        __syncthreads();
        for (int idx = tid; idx < MT * 16; idx += 256) {
            int r = idx >> 4, k = (idx & 15) * 4;
            int m = m0b + r;
            float x[4] = {0.f, 0.f, 0.f, 0.f};
            if (m < M) {
                if (GATHER_SWISH) {
                    float4 a = *(const float4*)&Ain[(size_t)s_src[r] * K + kc * 64 + k];
                    float4 b = *(const float4*)&Ain[(size_t)s_dst[r] * K + kc * 64 + k];
                    x[0] = swish(a.x + b.x); x[1] = swish(a.y + b.y);
                    x[2] = swish(a.z + b.z); x[3] = swish(a.w + b.w);
                } else {
                    float4 a = *(const float4*)&Ain[(size_t)m * K + kc * 64 + k];
                    x[0] = a.x; x[1] = a.y; x[2] = a.z; x[3] = a.w;
                }
            }
            #pragma unroll
            for (int j = 0; j < 4; j++) {
                __half hi, lo;
                split_h(x[j], hi, lo);
                Ah[r * HP + k + j] = hi;
                Al[r * HP + k + j] = lo;
            }
        }
        for (int idx = tid; idx < 128 * 16; idx += 256) {
            int n = idx & 127, kl = (idx >> 7) * 4;
            #pragma unroll
            for (int j = 0; j < 4; j++) {
                float w = W[(size_t)(kc * 64 + kl + j) * ldw + col0 + n];
                __half hi, lo;
                split_h(w, hi, lo);
                Bh[n * HP + kl + j] = hi;
                Bl[n * HP + kl + j] = lo;
            }
        }
        __syncthreads();

        #pragma unroll
        for (int ks = 0; ks < 4; ks++) {
            int kl = ks * 16;
            unsigned ah[2][4], al[2][4];
            #pragma unroll
            for (int mi = 0; mi < 2; mi++) {
                int r = wm0 + mi * 16;
                ah[mi][0] = *(const unsigned*)&Ah[(r + g) * HP + kl + 2 * tq];
                ah[mi][1] = *(const unsigned*)&Ah[(r + g + 8) * HP + kl + 2 * tq];
                ah[mi][2] = *(const unsigned*)&Ah[(r + g) * HP + kl + 8 + 2 * tq];
                ah[mi][3] = *(const unsigned*)&Ah[(r + g + 8) * HP + kl + 8 + 2 * tq];
                al[mi][0] = *(const unsigned*)&Al[(r + g) * HP + kl + 2 * tq];
                al[mi][1] = *(const unsigned*)&Al[(r + g + 8) * HP + kl + 2 * tq];
                al[mi][2] = *(const unsigned*)&Al[(r + g) * HP + kl + 8 + 2 * tq];
                al[mi][3] = *(const unsigned*)&Al[(r + g + 8) * HP + kl + 8 + 2 * tq];
            }
            #pragma unroll
            for (int ni = 0; ni < NI; ni++) {
                int n = n0w + ni * 8 + g;
                unsigned bh[2], bl[2];
                bh[0] = *(const unsigned*)&Bh[n * HP + kl + 2 * tq];
                bh[1] = *(const unsigned*)&Bh[n * HP + kl + 8 + 2 * tq];
                bl[0] = *(const unsigned*)&Bl[n * HP + kl + 2 * tq];
                bl[1] = *(const unsigned*)&Bl[n * HP + kl + 8 + 2 * tq];
                #pragma unroll
                for (int mi = 0; mi < 2; mi++) {
                    hmma(acc[mi][ni], ah[mi], bh);
                    hmma(acc[mi][ni], ah[mi], bl);
                    hmma(acc[mi][ni], al[mi], bh);
                }
            }
        }
    }

    #pragma unroll
    for (int mi = 0; mi < 2; mi++) {
        #pragma unroll
        for (int ni = 0; ni < NI; ni++) {
            int col = n0w + ni * 8 + 2 * tq;
            float2 bb = *(const float2*)&bias[col0 + col];
            bb.x *= bias_scale; bb.y *= bias_scale;
            #pragma unroll
            for (int h = 0; h < 2; h++) {
                int r = wm0 + mi * 16 + g + h * 8;
                int m = m0b + r;
                if (m >= M) continue;
                float2 o;
                o.x = acc[mi][ni][2 * h + 0] + bb.x;
                o.y = acc[mi][ni][2 * h + 1] + bb.y;
                if (SWISH_OUT) { o.x = swish(o.x); o.y = swish(o.y); }
                size_t ci = (size_t)m * ldw + col0 + col;
                if (RBF0) {
                    float dx = s_deb[col], dy = s_deb[col + 1];
                    const float* rrow = &s_rbfv[r * RB];
                    #pragma unroll
                    for (int k = 0; k < RB; k++) {
                        float rv = rrow[k];
                        dx = fmaf(rv, s_dew[k * 128 + col],     dx);
                        dy = fmaf(rv, s_dew[k * 128 + col + 1], dy);
                    }
                    float ev = s_envv[r];
                    o.x += ev * dx;
                    o.y += ev * dy;
                } else if (ACCUM) {
                    float2 old = *(const float2*)&C[ci];
                    o.x += old.x; o.y += old.y;
                }
                *(float2*)&C[ci] = o;
            }
        }
    }
}

// ---------------- CSR message pass: smem-staged edge metadata ----------------
constexpr int ETILE = 32;
__global__ void __launch_bounds__(128)
msg2_kernel(const int* __restrict__ nbrs, const float* __restrict__ dw,
            const float* __restrict__ db, int sel) {
    __shared__ int   s_dst[ETILE];
    __shared__ float s_env[ETILE];
    __shared__ float s_unit[ETILE][4];
    __shared__ __align__(16) float s_rbf[ETILE][RB];

    int n = blockIdx.x;
    int t = threadIdx.x;

    float dwr0[RB], dwr1[RB], dwr2[RB];
    #pragma unroll
    for (int k = 0; k < RB; k++) {
        dwr0[k] = dw[k * 384 + t];
        dwr1[k] = dw[k * 384 + t + 128];
        dwr2[k] = dw[k * 384 + t + 256];
    }
    float db0 = db[t], db1 = db[t + 128], db2 = db[t + 256];

    const float* vold = sel ? g_v1 : g_v0;
    float*       vnew = sel ? g_v0 : g_v1;

    int start = g_rowptr[n], end = g_rowptr[n + 1];
    float accs = 0.f, av0 = 0.f, av1 = 0.f, av2 = 0.f;

    for (int tile = start; tile < end; tile += ETILE) {
        int m = min(ETILE, end - tile);
        __syncthreads();
        if (t < m) {
            int e = g_perm[tile + t];
            s_dst[t] = nbrs[2 * e + 1];
            s_env[t] = g_env[e];
            s_unit[t][0] = g_unit[(size_t)e * 3 + 0];
            s_unit[t][1] = g_unit[(size_t)e * 3 + 1];
            s_unit[t][2] = g_unit[(size_t)e * 3 + 2];
        }
        for (int idx = t; idx < m * 5; idx += 128) {
            int le = idx / 5, q = idx - le * 5;
            int e = g_perm[tile + le];
            ((float4*)s_rbf[le])[q] = ((const float4*)&g_rbf[(size_t)e * RB])[q];
        }
        __syncthreads();

        for (int le = 0; le < m; le++) {
            const float4* rb4 = (const float4*)s_rbf[le];
            float4 r0 = rb4[0], r1 = rb4[1], r2 = rb4[2], r3 = rb4[3], r4 = rb4[4];
            float rb[RB] = {r0.x, r0.y, r0.z, r0.w, r1.x, r1.y, r1.z, r1.w,
                            r2.x, r2.y, r2.z, r2.w, r3.x, r3.y, r3.z, r3.w,
                            r4.x, r4.y, r4.z, r4.w};
            float a0 = db0, a1 = db1, a2 = db2;
            #pragma unroll
            for (int k = 0; k < RB; k++) {
                a0 = fmaf(rb[k], dwr0[k], a0);
                a1 = fmaf(rb[k], dwr1[k], a1);
                a2 = fmaf(rb[k], dwr2[k], a2);
            }
            float env = s_env[le];
            a0 *= env; a1 *= env; a2 *= env;

            int dst = s_dst[le];
            const float* ph = g_phi + (size_t)dst * 384;
            float s0 = ph[t] * a0;
            float s1 = ph[t + 128] * a1;
            float s2 = ph[t + 256] * a2;
            accs += s1;

            const float* vo = vold + (size_t)dst * 384 + 3 * t;
            av0 += fmaf(s0, vo[0], s2 * s_unit[le][0]);
            av1 += fmaf(s0, vo[1], s2 * s_unit[le][1]);
            av2 += fmaf(s0, vo[2], s2 * s_unit[le][2]);
        }
    }

    g_s[(size_t)n * 128 + t] += accs;
    const float* vs = vold + (size_t)n * 384 + 3 * t;
    float*       vp = vnew + (size_t)n * 384 + 3 * t;
    vp[0] = vs[0] + av0;
    vp[1] = vs[1] + av1;
    vp[2] = vs[2] + av2;
}

// ---------------- update stage 1 ----------------
constexpr int TA = 8;
__global__ void __launch_bounds__(128)
upd1_kernel(const float* __restrict__ U, const float* __restrict__ Vw, int sel) {
    __shared__ __align__(16) float v_s[TA * 384];
    int t = threadIdx.x;
    int n0 = blockIdx.x * TA;
    const float* vcur = sel ? g_v1 : g_v0;

    for (int i = t; i < TA * 384; i += 128) {
        size_t gi = (size_t)n0 * 384 + i;
        v_s[i] = (gi < (size_t)NN * 384) ? vcur[gi] : 0.f;
    }
    __syncthreads();

    float uv[TA][3], vv[TA][3];
    #pragma unroll
    for (int a = 0; a < TA; a++)
        #pragma unroll
        for (int d = 0; d < 3; d++) { uv[a][d] = 0.f; vv[a][d] = 0.f; }

    for (int f4 = 0; f4 < 32; f4++) {
        float u0 = U[(f4 * 4 + 0) * 128 + t];
        float u1 = U[(f4 * 4 + 1) * 128 + t];
        float u2 = U[(f4 * 4 + 2) * 128 + t];
        float u3 = U[(f4 * 4 + 3) * 128 + t];
        float w0 = Vw[(f4 * 4 + 0) * 128 + t];
        float w1 = Vw[(f4 * 4 + 1) * 128 + t];
        float w2 = Vw[(f4 * 4 + 2) * 128 + t];
        float w3 = Vw[(f4 * 4 + 3) * 128 + t];
        #pragma unroll
        for (int a = 0; a < TA; a++) {
            const float4* vp = reinterpret_cast<const float4*>(&v_s[a * 384 + f4 * 12]);
            float4 p0 = vp[0], p1 = vp[1], p2 = vp[2];
            uv[a][0] = fmaf(p0.x, u0, fmaf(p0.w, u1, fmaf(p1.z, u2, fmaf(p2.y, u3, uv[a][0]))));
            uv[a][1] = fmaf(p0.y, u0, fmaf(p1.x, u1, fmaf(p1.w, u2, fmaf(p2.z, u3, uv[a][1]))));
            uv[a][2] = fmaf(p0.z, u0, fmaf(p1.y, u1, fmaf(p2.x, u2, fmaf(p2.w, u3, uv[a][2]))));
            vv[a][0] = fmaf(p0.x, w0, fmaf(p0.w, w1, fmaf(p1.z, w2, fmaf(p2.y, w3, vv[a][0]))));
            vv[a][1] = fmaf(p0.y, w0, fmaf(p1.x, w1, fmaf(p1.w, w2, fmaf(p2.z, w3, vv[a][1]))));
            vv[a][2] = fmaf(p0.z, w0, fmaf(p1.y, w1, fmaf(p2.x, w2, fmaf(p2.w, w3, vv[a][2]))));
        }
    }

    #pragma unroll
    for (int a = 0; a < TA; a++) {
        int n = n0 + a;
        if (n >= NN) break;
        float dt = uv[a][0] * vv[a][0] + uv[a][1] * vv[a][1] + uv[a][2] * vv[a][2];
        float vn = sqrtf(vv[a][0] * vv[a][0] + vv[a][1] * vv[a][1] + vv[a][2] * vv[a][2] + EPS3);
        g_uv[(size_t)n * 384 + 3 * t + 0] = uv[a][0];
        g_uv[(size_t)n * 384 + 3 * t + 1] = uv[a][1];
        g_uv[(size_t)n * 384 + 3 * t + 2] = uv[a][2];
        g_dot[(size_t)n * 128 + t] = dt;
        g_stk[(size_t)n * 256 + t] = g_s[(size_t)n * 128 + t];
        g_stk[(size_t)n * 256 + 128 + t] = vn;
    }
}

// ---------------- update apply ----------------
__global__ void apply_kernel(int sel) {
    int i = blockIdx.x * blockDim.x + threadIdx.x;
    if (i >= NN * 128) return;
    int n = i >> 7, g = i & 127;
    float avv = g_spl[(size_t)n * 384 + g];
    float asv = g_spl[(size_t)n * 384 + 128 + g];
    float ass = g_spl[(size_t)n * 384 + 256 + g];
    float* v = (sel ? g_v1 : g_v0) + (size_t)n * 384 + 3 * g;
    const float* uv = g_uv + (size_t)n * 384 + 3 * g;
    v[0] += uv[0] * avv;
    v[1] += uv[1] * avv;
    v[2] += uv[2] * avv;
    g_s[i] += g_dot[i] * asv + ass;
}

// ================ HMMA fused readout ================
constexpr int HP2 = 136;
__global__ void __launch_bounds__(256)
readout_mma(const float* __restrict__ W1, const float* __restrict__ b1,
            const float* __restrict__ w2, const float* __restrict__ b2,
            const int* __restrict__ nbrs, float* __restrict__ out) {
    extern __shared__ __align__(16) __half hsm[];
    __half* Ah = hsm;
    __half* Al = Ah + 128 * HP2;
    __half* Bh = Al + 128 * HP2;
    __half* Bl = Bh + 128 * HP2;
    __shared__ float red[128][2];

    int tid = threadIdx.x;
    int wid = tid >> 5, lane = tid & 31;
    int g = lane >> 2, tq = lane & 3;
    int m0 = (wid & 3) * 32;
    int n0w = (wid >> 2) * 64;
    int nw = wid >> 2;
    int e0 = blockIdx.x * 128;

    for (int idx = tid; idx < 128 * 32; idx += 256) {
        int e = idx >> 5, k = (idx & 31) * 4;
        float4 a = *(const float4*)&g_eij[(size_t)(e0 + e) * 128 + k];
        float x[4] = {a.x, a.y, a.z, a.w};
        #pragma unroll
        for (int j = 0; j < 4; j++) {
            __half hi, lo;
            split_h(x[j], hi, lo);
            Ah[e * HP2 + k + j] = hi;
            Al[e * HP2 + k + j] = lo;
        }
    }

    float rs[2][2] = {{0.f, 0.f}, {0.f, 0.f}};

    for (int nc = 0; nc < 2; nc++) {
        __syncthreads();
        for (int idx = tid; idx < 128 * 32; idx += 256) {
            int n = idx & 127, k = (idx >> 7) * 4;
            #pragma unroll
            for (int j = 0; j < 4; j++) {
                float w = W1[(size_t)(k + j) * 256 + nc * 128 + n];
                __half hi, lo;
                split_h(w, hi, lo);
                Bh[n * HP2 + k + j] = hi;
                Bl[n * HP2 + k + j] = lo;
            }
        }
        __syncthreads();

        float acc[2][8][4];
        #pragma unroll
        for (int mi = 0; mi < 2; mi++)
            #pragma unroll
            for (int ni = 0; ni < 8; ni++)
                #pragma unroll
                for (int j = 0; j < 4; j++) acc[mi][ni][j] = 0.f;

        #pragma unroll
        for (int ks = 0; ks < 8; ks++) {
            int kl = ks * 16;
            unsigned ah[2][4], al[2][4];
            #pragma unroll
            for (int mi = 0; mi < 2; mi++) {
                int r = m0 + mi * 16;
                ah[mi][0] = *(const unsigned*)&Ah[(r + g) * HP2 + kl + 2 * tq];
                ah[mi][1] = *(const unsigned*)&Ah[(r + g + 8) * HP2 + kl + 2 * tq];
                ah[mi][2] = *(const unsigned*)&Ah[(r + g) * HP2 + kl + 8 + 2 * tq];
                ah[mi][3] = *(const unsigned*)&Ah[(r + g + 8) * HP2 + kl + 8 + 2 * tq];
                al[mi][0] = *(const unsigned*)&Al[(r + g) * HP2 + kl + 2 * tq];
                al[mi][1] = *(const unsigned*)&Al[(r + g + 8) * HP2 + kl + 2 * tq];
                al[mi][2] = *(const unsigned*)&Al[(r + g) * HP2 + kl + 8 + 2 * tq];
                al[mi][3] = *(const unsigned*)&Al[(r + g + 8) * HP2 + kl + 8 + 2 * tq];
            }
            #pragma unroll
            for (int ni = 0; ni < 8; ni++) {
                int n = n0w + ni * 8 + g;
                unsigned bh[2], bl[2];
                bh[0] = *(const unsigned*)&Bh[n * HP2 + kl + 2 * tq];
                bh[1] = *(const unsigned*)&Bh[n * HP2 + kl + 8 + 2 * tq];
                bl[0] = *(const unsigned*)&Bl[n * HP2 + kl + 2 * tq];
                bl[1] = *(const unsigned*)&Bl[n * HP2 + kl + 8 + 2 * tq];
                #pragma unroll
                for (int mi = 0; mi < 2; mi++) {
                    hmma(acc[mi][ni], ah[mi], bh);
                    hmma(acc[mi][ni], ah[mi], bl);
                    hmma(acc[mi][ni], al[mi], bh);
                }
            }
        }

        #pragma unroll
        for (int mi = 0; mi < 2; mi++) {
            #pragma unroll
            for (int ni = 0; ni < 8; ni++) {
                int c = nc * 128 + n0w + ni * 8 + 2 * tq;
                float2 bb = *(const float2*)&b1[c];
                float2 ww = *(const float2*)&w2[c];
                rs[mi][0] += swish(acc[mi][ni][0] + bb.x) * ww.x
                           + swish(acc[mi][ni][1] + bb.y) * ww.y;
                rs[mi][1] += swish(acc[mi][ni][2] + bb.x) * ww.x
                           + swish(acc[mi][ni][3] + bb.y) * ww.y;
            }
        }
    }

    #pragma unroll
    for (int mi = 0; mi < 2; mi++) {
        #pragma unroll
        for (int h = 0; h < 2; h++) {
            float v = rs[mi][h];
            v += __shfl_xor_sync(0xffffffff, v, 1);
            v += __shfl_xor_sync(0xffffffff, v, 2);
            rs[mi][h] = v;
        }
    }
    if (tq == 0) {
        red[m0 + g][nw]          = rs[0][0];
        red[m0 + g + 8][nw]      = rs[0][1];
        red[m0 + 16 + g][nw]     = rs[1][0];
        red[m0 + 16 + g + 8][nw] = rs[1][1];
    }
    __syncthreads();

    if (tid < 128) {
        int e = e0 + tid;
        float s = red[tid][0] + red[tid][1] + b2[0];
        int src = nbrs[2 * e], dst = nbrs[2 * e + 1];
        float fx = s * g_unit[(size_t)e * 3 + 0];
        float fy = s * g_unit[(size_t)e * 3 + 1];
        float fz = s * g_unit[(size_t)e * 3 + 2];
        atomicAdd(&out[src * 3 + 0], fx);
        atomicAdd(&out[src * 3 + 1], fy);
        atomicAdd(&out[src * 3 + 2], fz);
        atomicAdd(&out[dst * 3 + 0], -fx);
        atomicAdd(&out[dst * 3 + 1], -fy);
        atomicAdd(&out[dst * 3 + 2], -fz);
    }
}

// ---------------- host launcher ----------------
extern "C" void kernel_launch(void* const* d_in, const int* in_sizes, int n_in,
                              void* d_out, int out_size) {
    const float* xyz     = (const float*)d_in[0];
    const int*   z       = (const int*)  d_in[1];
    const int*   nbrs    = (const int*)  d_in[2];
    const float* emb     = (const float*)d_in[3];
    const float* de_w    = (const float*)d_in[4];
    const float* de_b    = (const float*)d_in[5];
    const float* msg_w1  = (const float*)d_in[6];
    const float* msg_b1  = (const float*)d_in[7];
    const float* msg_w2  = (const float*)d_in[8];
    const float* msg_b2  = (const float*)d_in[9];
    const float* msg_dw  = (const float*)d_in[10];
    const float* msg_db  = (const float*)d_in[11];
    const float* upd_u   = (const float*)d_in[12];
    const float* upd_v   = (const float*)d_in[13];
    const float* upd_w1  = (const float*)d_in[14];
    const float* upd_b1  = (const float*)d_in[15];
    const float* upd_w2  = (const float*)d_in[16];
    const float* upd_b2  = (const float*)d_in[17];
    const float* edge_w1 = (const float*)d_in[18];
    const float* edge_b1 = (const float*)d_in[19];
    const float* edge_w2 = (const float*)d_in[20];
    const float* edge_b2 = (const float*)d_in[21];
    const float* ro_w1   = (const float*)d_in[22];
    const float* ro_b1   = (const float*)d_in[23];
    const float* ro_w2   = (const float*)d_in[24];
    const float* ro_b2   = (const float*)d_in[25];
    float* out = (float*)d_out;

    float *p_rbf, *p_env, *p_eij, *p_s, *p_phi, *p_h1, *p_stk, *p_spl, *p_t;
    cudaGetSymbolAddress((void**)&p_rbf,  g_rbf);
    cudaGetSymbolAddress((void**)&p_env,  g_env);
    cudaGetSymbolAddress((void**)&p_eij,  g_eij);
    cudaGetSymbolAddress((void**)&p_s,    g_s);
    cudaGetSymbolAddress((void**)&p_phi,  g_phi);
    cudaGetSymbolAddress((void**)&p_h1,   g_h1);
    cudaGetSymbolAddress((void**)&p_stk,  g_stk);
    cudaGetSymbolAddress((void**)&p_spl,  g_spl);
    cudaGetSymbolAddress((void**)&p_t,    g_t);

    const int SMEM_E = (2 * 128 + 2 * 128) * HP * 2;  // 73728 (MT=128)
    const int SMEM_N = (2 * 64 + 2 * 128) * HP * 2;   // 55296 (MT=64)
    const int SMEM_RO = 4 * 128 * HP2 * 2;            // 139264
    cudaFuncSetAttribute(hmma_gemm<64, 128, false, true,  false, false>,
                         cudaFuncAttributeMaxDynamicSharedMemorySize, SMEM_N);
    cudaFuncSetAttribute(hmma_gemm<64, 128, false, false, false, false>,
                         cudaFuncAttributeMaxDynamicSharedMemorySize, SMEM_N);
    cudaFuncSetAttribute(hmma_gemm<64, 256, false, true,  false, false>,
                         cudaFuncAttributeMaxDynamicSharedMemorySize, SMEM_N);
    cudaFuncSetAttribute(hmma_gemm<128, 256, true, false, true,  false>,
                         cudaFuncAttributeMaxDynamicSharedMemorySize, SMEM_E);
    cudaFuncSetAttribute(hmma_gemm<128, 256, true, false, false, true>,
                         cudaFuncAttributeMaxDynamicSharedMemorySize, SMEM_E);
    cudaFuncSetAttribute(readout_mma,
                         cudaFuncAttributeMaxDynamicSharedMemorySize, SMEM_RO);

    const int gN = (NN + 63) / 64;    // 313  (node GEMMs, MT=64)
    const int gE = EE / 128;          // 2500 (edge GEMMs, MT=128)

    init_kernel<<<2048, 256>>>(emb, z, out);
    prep_kernel<<<(EE + 255) / 256, 256>>>(xyz, nbrs);

    // CSR build
    zero_rowptr<<<(NN + 256) / 256, 256>>>();
    hist_kernel<<<(EE + 255) / 256, 256>>>(nbrs);
    scan_kernel<<<1, 1024>>>();      // also fills g_cursor
    scatter_kernel<<<(EE + 255) / 256, 256>>>(nbrs);

    for (int l = 0; l < 3; l++) {
        int sel = l & 1;
        int cur = sel ^ 1;

        // phi = swish(s @ msg_w1 + b1) @ msg_w2 + b2
        hmma_gemm<64, 128, false, true, false, false><<<dim3(gN, 1), 256, SMEM_N>>>(
            p_s, msg_w1 + l * 128 * 128, 128, msg_b1 + l * 128, 1.f, p_h1, nullptr, NN,
            nullptr, nullptr, nullptr, nullptr);
        hmma_gemm<64, 128, false, false, false, false><<<dim3(gN, 3), 256, SMEM_N>>>(
            p_h1, msg_w2 + l * 128 * 384, 384, msg_b2 + l * 384, 1.f, p_phi, nullptr, NN,
            nullptr, nullptr, nullptr, nullptr);

        // CSR message pass (smem-staged)
        msg2_kernel<<<NN, 128>>>(nbrs, msg_dw + l * RB * 384, msg_db + l * 384, sel);

        // update block
        upd1_kernel<<<(NN + TA - 1) / TA, 128>>>(upd_u + l * 128 * 128,
                                                 upd_v + l * 128 * 128, cur);
        hmma_gemm<64, 256, false, true, false, false><<<dim3(gN, 1), 256, SMEM_N>>>(
            p_stk, upd_w1 + l * 256 * 128, 128, upd_b1 + l * 128, 1.f, p_h1, nullptr, NN,
            nullptr, nullptr, nullptr, nullptr);
        hmma_gemm<64, 128, false, false, false, false><<<dim3(gN, 3), 256, SMEM_N>>>(
            p_h1, upd_w2 + l * 128 * 384, 384, upd_b2 + l * 384, 1.f, p_spl, nullptr, NN,
            nullptr, nullptr, nullptr, nullptr);
        apply_kernel<<<(NN * 128 + 255) / 256, 256>>>(cur);

        // edge MLP (factored): t per node
        hmma_gemm<64, 128, false, false, false, false><<<dim3(gN, 2), 256, SMEM_N>>>(
            p_s, edge_w1 + l * 128 * 256, 256, edge_b1 + l * 256, 0.5f, p_t, nullptr, NN,
            nullptr, nullptr, nullptr, nullptr);

        if (l == 0) {
            // edge2 with fused eij-init term in epilogue (write, not accumulate)
            hmma_gemm<128, 256, true, false, false, true><<<dim3(gE, 1), 256, SMEM_E>>>(
                p_t, edge_w2, 128, edge_b2, 1.f, p_eij, nbrs, EE,
                p_rbf, p_env, de_w, de_b);
        } else {
            hmma_gemm<128, 256, true, false, true, false><<<dim3(gE, 1), 256, SMEM_E>>>(
                p_t, edge_w2 + l * 256 * 128, 128, edge_b2 + l * 128, 1.f, p_eij, nbrs, EE,
                nullptr, nullptr, nullptr, nullptr);
        }
    }

    // fused HMMA readout
    readout_mma<<<gE, 256, SMEM_RO>>>(ro_w1, ro_b1, ro_w2, ro_b2, nbrs, out);

    (void)in_sizes; (void)n_in; (void)out_size;
}

// round 16
// speedup vs baseline: 1.0266x; 1.0108x over previous
#include <cuda_runtime.h>
#include <cuda_fp16.h>
#include <math.h>

// ---------------- problem constants ----------------
constexpr int NN = 20000;
constexpr int EE = 320000;
constexpr int RB = 20;    // NRBF
constexpr float PI_F = 3.14159265358979323846f;
constexpr float EPS3 = 3e-15f;

// ---------------- device scratch ----------------
__device__ float g_rbf [(size_t)EE * RB];
__device__ float g_env [EE];
__device__ float g_unit[(size_t)EE * 3];
__device__ float g_eij [(size_t)EE * 128];
__device__ float g_s   [(size_t)NN * 128];
__device__ float g_v0  [(size_t)NN * 384];
__device__ float g_v1  [(size_t)NN * 384];
__device__ float g_phi [(size_t)NN * 384];
__device__ float g_h1  [(size_t)NN * 128];
__device__ float g_uv  [(size_t)NN * 384];
__device__ float g_dot [(size_t)NN * 128];
__device__ float g_stk [(size_t)NN * 256];
__device__ float g_spl [(size_t)NN * 384];
__device__ float g_tA  [(size_t)NN * 256];   // t buffer, layer 0
__device__ float g_tB  [(size_t)NN * 256];   // t buffer, layer 1
__device__ float g_tC  [(size_t)NN * 256];   // t buffer, layer 2
// CSR by src
__device__ int g_rowptr[NN + 1];
__device__ int g_cursor[NN];
__device__ int g_perm  [EE];

__device__ __forceinline__ float swish(float x) {
    return x / (1.f + __expf(-x));
}

__device__ __forceinline__ void split_h(float x, __half& hi, __half& lo) {
    hi = __float2half_rn(x);
    lo = __float2half_rn(x - __half2float(hi));
}

__device__ __forceinline__ void hmma(float* d, const unsigned* a, const unsigned* b) {
    asm volatile(
        "mma.sync.aligned.m16n8k16.row.col.f32.f16.f16.f32 "
        "{%0,%1,%2,%3}, {%4,%5,%6,%7}, {%8,%9}, {%0,%1,%2,%3};"
        : "+f"(d[0]), "+f"(d[1]), "+f"(d[2]), "+f"(d[3])
        : "r"(a[0]), "r"(a[1]), "r"(a[2]), "r"(a[3]), "r"(b[0]), "r"(b[1]));
}

// ---------------- init ----------------
__global__ void init_kernel(const float* __restrict__ emb, const int* __restrict__ z,
                            float* __restrict__ out) {
    int stride = gridDim.x * blockDim.x;
    for (int i = blockIdx.x * blockDim.x + threadIdx.x; i < NN * 384; i += stride) {
        g_v0[i] = 0.f;
        if (i < NN * 128) {
            int n = i >> 7, f = i & 127;
            g_s[i] = emb[z[n] * 128 + f];
        }
        if (i < NN * 3) out[i] = 0.f;
    }
}

// ---------------- CSR build ----------------
__global__ void zero_rowptr() {
    int i = blockIdx.x * blockDim.x + threadIdx.x;
    if (i <= NN) g_rowptr[i] = 0;
}
__global__ void hist_kernel(const int* __restrict__ nbrs) {
    int e = blockIdx.x * blockDim.x + threadIdx.x;
    if (e < EE) atomicAdd(&g_rowptr[nbrs[2 * e] + 1], 1);
}
__global__ void scan_kernel() {
    __shared__ int sm[1024];
    __shared__ int carry;
    int t = threadIdx.x;
    if (t == 0) carry = 0;
    __syncthreads();
    int nch = (NN + 1 + 1023) / 1024;
    for (int c = 0; c < nch; c++) {
        int i = c * 1024 + t;
        int v = (i <= NN) ? g_rowptr[i] : 0;
        sm[t] = v;
        __syncthreads();
        #pragma unroll
        for (int off = 1; off < 1024; off <<= 1) {
            int x = (t >= off) ? sm[t - off] : 0;
            __syncthreads();
            sm[t] += x;
            __syncthreads();
        }
        if (i <= NN) {
            int val = sm[t] + carry;
            g_rowptr[i] = val;
            if (i < NN) g_cursor[i] = val;
        }
        int total = sm[1023];
        __syncthreads();
        if (t == 0) carry += total;
        __syncthreads();
    }
}
__global__ void scatter_kernel(const int* __restrict__ nbrs) {
    int e = blockIdx.x * blockDim.x + threadIdx.x;
    if (e < EE) {
        int pos = atomicAdd(&g_cursor[nbrs[2 * e]], 1);
        g_perm[pos] = e;
    }
}

// ---------------- per-edge geometry ----------------
__global__ void prep_kernel(const float* __restrict__ xyz, const int* __restrict__ nbrs) {
    int e = blockIdx.x * blockDim.x + threadIdx.x;
    if (e >= EE) return;
    int s = nbrs[2 * e], d = nbrs[2 * e + 1];
    float dx = xyz[d * 3 + 0] - xyz[s * 3 + 0];
    float dy = xyz[d * 3 + 1] - xyz[s * 3 + 1];
    float dz = xyz[d * 3 + 2] - xyz[s * 3 + 2];
    float d2 = dx * dx + dy * dy + dz * dz + EPS3;
    float dist = sqrtf(d2);
    float inv = 1.f / dist;
    g_unit[(size_t)e * 3 + 0] = dx * inv;
    g_unit[(size_t)e * 3 + 1] = dy * inv;
    g_unit[(size_t)e * 3 + 2] = dz * inv;
    float env = (dist < 5.f) ? 0.5f * (cosf(dist * (PI_F / 5.f)) + 1.f) : 0.f;
    g_env[e] = env;
    float base = dist * (PI_F / 5.f);
    #pragma unroll
    for (int k = 1; k <= RB; k++) {
        g_rbf[(size_t)e * RB + (k - 1)] = sinf(base * (float)k) * inv;
    }
}

// ================ generic HMMA GEMM ================
// MT: rows per block (128 or 64). RBF0 valid only with MT=128.
constexpr int HP = 72;
template<int MT, int K, bool GATHER_SWISH, bool SWISH_OUT, bool ACCUM, bool RBF0>
__global__ void __launch_bounds__(256, MT == 128 ? 2 : 3)
hmma_gemm(const float* __restrict__ Ain, const float* __restrict__ W, int ldw,
          const float* __restrict__ bias, float bias_scale, float* __restrict__ C,
          const int* __restrict__ nbrs, int M,
          const float* __restrict__ rbfp, const float* __restrict__ envp,
          const float* __restrict__ dew,  const float* __restrict__ deb) {
    extern __shared__ __align__(16) __half hsm[];
    __half* Ah = hsm;
    __half* Al = Ah + MT * HP;
    __half* Bh = Al + MT * HP;
    __half* Bl = Bh + 128 * HP;
    __shared__ int s_src[128], s_dst[128];
    __shared__ __align__(16) float s_dew [RBF0 ? RB * 128 : 1];
    __shared__ __align__(16) float s_rbfv[RBF0 ? 128 * RB : 1];
    __shared__ float s_envv[RBF0 ? 128 : 1];
    __shared__ float s_deb [RBF0 ? 128 : 1];

    constexpr int MW = (MT == 128) ? 4 : 2;   // m-warp groups
    constexpr int NI = (MT == 128) ? 8 : 4;   // 8-col groups per warp

    int tid = threadIdx.x;
    int wid = tid >> 5, lane = tid & 31;
    int g = lane >> 2, tq = lane & 3;
    int wm0 = (wid % MW) * 32;
    int n0w = (wid / MW) * (NI * 8);
    int m0b = blockIdx.x * MT;
    int col0 = blockIdx.y * 128;

    if (GATHER_SWISH && tid < MT) {
        int m = m0b + tid;
        s_src[tid] = (m < M) ? nbrs[2 * m] : 0;
        s_dst[tid] = (m < M) ? nbrs[2 * m + 1] : 0;
    }
    if (RBF0) {
        for (int i = tid; i < RB * 128; i += 256) s_dew[i] = dew[i];
        for (int idx = tid; idx < 128 * 5; idx += 256) {
            int r = idx / 5, q = idx - r * 5;
            ((float4*)&s_rbfv[r * RB])[q] =
                ((const float4*)&rbfp[(size_t)(m0b + r) * RB])[q];
        }
        if (tid < 128) {
            s_envv[tid] = envp[m0b + tid];
            s_deb[tid]  = deb[tid];
        }
    }

    float acc[2][NI][4];
    #pragma unroll
    for (int mi = 0; mi < 2; mi++)
        #pragma unroll
        for (int ni = 0; ni < NI; ni++)
            #pragma unroll
            for (int j = 0; j < 4; j++) acc[mi][ni][j] = 0.f;

    constexpr int NCH = K / 64;
    for (int kc = 0; kc < NCH; kc++) {
        __syncthreads();
        for (int idx = tid; idx < MT * 16; idx += 256) {
            int r = idx >> 4, k = (idx & 15) * 4;
            int m = m0b + r;
            float x[4] = {0.f, 0.f, 0.f, 0.f};
            if (m < M) {
                if (GATHER_SWISH) {
                    float4 a = *(const float4*)&Ain[(size_t)s_src[r] * K + kc * 64 + k];
                    float4 b = *(const float4*)&Ain[(size_t)s_dst[r] * K + kc * 64 + k];
                    x[0] = swish(a.x + b.x); x[1] = swish(a.y + b.y);
                    x[2] = swish(a.z + b.z); x[3] = swish(a.w + b.w);
                } else {
                    float4 a = *(const float4*)&Ain[(size_t)m * K + kc * 64 + k];
                    x[0] = a.x; x[1] = a.y; x[2] = a.z; x[3] = a.w;
                }
            }
            #pragma unroll
            for (int j = 0; j < 4; j++) {
                __half hi, lo;
                split_h(x[j], hi, lo);
                Ah[r * HP + k + j] = hi;
                Al[r * HP + k + j] = lo;
            }
        }
        for (int idx = tid; idx < 128 * 16; idx += 256) {
            int n = idx & 127, kl = (idx >> 7) * 4;
            #pragma unroll
            for (int j = 0; j < 4; j++) {
                float w = W[(size_t)(kc * 64 + kl + j) * ldw + col0 + n];
                __half hi, lo;
                split_h(w, hi, lo);
                Bh[n * HP + kl + j] = hi;
                Bl[n * HP + kl + j] = lo;
            }
        }
        __syncthreads();

        #pragma unroll
        for (int ks = 0; ks < 4; ks++) {
            int kl = ks * 16;
            unsigned ah[2][4], al[2][4];
            #pragma unroll
            for (int mi = 0; mi < 2; mi++) {
                int r = wm0 + mi * 16;
                ah[mi][0] = *(const unsigned*)&Ah[(r + g) * HP + kl + 2 * tq];
                ah[mi][1] = *(const unsigned*)&Ah[(r + g + 8) * HP + kl + 2 * tq];
                ah[mi][2] = *(const unsigned*)&Ah[(r + g) * HP + kl + 8 + 2 * tq];
                ah[mi][3] = *(const unsigned*)&Ah[(r + g + 8) * HP + kl + 8 + 2 * tq];
                al[mi][0] = *(const unsigned*)&Al[(r + g) * HP + kl + 2 * tq];
                al[mi][1] = *(const unsigned*)&Al[(r + g + 8) * HP + kl + 2 * tq];
                al[mi][2] = *(const unsigned*)&Al[(r + g) * HP + kl + 8 + 2 * tq];
                al[mi][3] = *(const unsigned*)&Al[(r + g + 8) * HP + kl + 8 + 2 * tq];
            }
            #pragma unroll
            for (int ni = 0; ni < NI; ni++) {
                int n = n0w + ni * 8 + g;
                unsigned bh[2], bl[2];
                bh[0] = *(const unsigned*)&Bh[n * HP + kl + 2 * tq];
                bh[1] = *(const unsigned*)&Bh[n * HP + kl + 8 + 2 * tq];
                bl[0] = *(const unsigned*)&Bl[n * HP + kl + 2 * tq];
                bl[1] = *(const unsigned*)&Bl[n * HP + kl + 8 + 2 * tq];
                #pragma unroll
                for (int mi = 0; mi < 2; mi++) {
                    hmma(acc[mi][ni], ah[mi], bh);
                    hmma(acc[mi][ni], ah[mi], bl);
                    hmma(acc[mi][ni], al[mi], bh);
                }
            }
        }
    }

    #pragma unroll
    for (int mi = 0; mi < 2; mi++) {
        #pragma unroll
        for (int ni = 0; ni < NI; ni++) {
            int col = n0w + ni * 8 + 2 * tq;
            float2 bb = *(const float2*)&bias[col0 + col];
            bb.x *= bias_scale; bb.y *= bias_scale;
            #pragma unroll
            for (int h = 0; h < 2; h++) {
                int r = wm0 + mi * 16 + g + h * 8;
                int m = m0b + r;
                if (m >= M) continue;
                float2 o;
                o.x = acc[mi][ni][2 * h + 0] + bb.x;
                o.y = acc[mi][ni][2 * h + 1] + bb.y;
                if (SWISH_OUT) { o.x = swish(o.x); o.y = swish(o.y); }
                size_t ci = (size_t)m * ldw + col0 + col;
                if (RBF0) {
                    float dx = s_deb[col], dy = s_deb[col + 1];
                    const float* rrow = &s_rbfv[r * RB];
                    #pragma unroll
                    for (int k = 0; k < RB; k++) {
                        float rv = rrow[k];
                        dx = fmaf(rv, s_dew[k * 128 + col],     dx);
                        dy = fmaf(rv, s_dew[k * 128 + col + 1], dy);
                    }
                    float ev = s_envv[r];
                    o.x += ev * dx;
                    o.y += ev * dy;
                } else if (ACCUM) {
                    float2 old = *(const float2*)&C[ci];
                    o.x += old.x; o.y += old.y;
                }
                *(float2*)&C[ci] = o;
            }
        }
    }
}

// ---------------- CSR message pass: smem-staged edge metadata ----------------
constexpr int ETILE = 32;
__global__ void __launch_bounds__(128)
msg2_kernel(const int* __restrict__ nbrs, const float* __restrict__ dw,
            const float* __restrict__ db, int sel) {
    __shared__ int   s_dst[ETILE];
    __shared__ float s_env[ETILE];
    __shared__ float s_unit[ETILE][4];
    __shared__ __align__(16) float s_rbf[ETILE][RB];

    int n = blockIdx.x;
    int t = threadIdx.x;

    float dwr0[RB], dwr1[RB], dwr2[RB];
    #pragma unroll
    for (int k = 0; k < RB; k++) {
        dwr0[k] = dw[k * 384 + t];
        dwr1[k] = dw[k * 384 + t + 128];
        dwr2[k] = dw[k * 384 + t + 256];
    }
    float db0 = db[t], db1 = db[t + 128], db2 = db[t + 256];

    const float* vold = sel ? g_v1 : g_v0;
    float*       vnew = sel ? g_v0 : g_v1;

    int start = g_rowptr[n], end = g_rowptr[n + 1];
    float accs = 0.f, av0 = 0.f, av1 = 0.f, av2 = 0.f;

    for (int tile = start; tile < end; tile += ETILE) {
        int m = min(ETILE, end - tile);
        __syncthreads();
        if (t < m) {
            int e = g_perm[tile + t];
            s_dst[t] = nbrs[2 * e + 1];
            s_env[t] = g_env[e];
            s_unit[t][0] = g_unit[(size_t)e * 3 + 0];
            s_unit[t][1] = g_unit[(size_t)e * 3 + 1];
            s_unit[t][2] = g_unit[(size_t)e * 3 + 2];
        }
        for (int idx = t; idx < m * 5; idx += 128) {
            int le = idx / 5, q = idx - le * 5;
            int e = g_perm[tile + le];
            ((float4*)s_rbf[le])[q] = ((const float4*)&g_rbf[(size_t)e * RB])[q];
        }
        __syncthreads();

        for (int le = 0; le < m; le++) {
            const float4* rb4 = (const float4*)s_rbf[le];
            float4 r0 = rb4[0], r1 = rb4[1], r2 = rb4[2], r3 = rb4[3], r4 = rb4[4];
            float rb[RB] = {r0.x, r0.y, r0.z, r0.w, r1.x, r1.y, r1.z, r1.w,
                            r2.x, r2.y, r2.z, r2.w, r3.x, r3.y, r3.z, r3.w,
                            r4.x, r4.y, r4.z, r4.w};
            float a0 = db0, a1 = db1, a2 = db2;
            #pragma unroll
            for (int k = 0; k < RB; k++) {
                a0 = fmaf(rb[k], dwr0[k], a0);
                a1 = fmaf(rb[k], dwr1[k], a1);
                a2 = fmaf(rb[k], dwr2[k], a2);
            }
            float env = s_env[le];
            a0 *= env; a1 *= env; a2 *= env;

            int dst = s_dst[le];
            const float* ph = g_phi + (size_t)dst * 384;
            float s0 = ph[t] * a0;
            float s1 = ph[t + 128] * a1;
            float s2 = ph[t + 256] * a2;
            accs += s1;

            const float* vo = vold + (size_t)dst * 384 + 3 * t;
            av0 += fmaf(s0, vo[0], s2 * s_unit[le][0]);
            av1 += fmaf(s0, vo[1], s2 * s_unit[le][1]);
            av2 += fmaf(s0, vo[2], s2 * s_unit[le][2]);
        }
    }

    g_s[(size_t)n * 128 + t] += accs;
    const float* vs = vold + (size_t)n * 384 + 3 * t;
    float*       vp = vnew + (size_t)n * 384 + 3 * t;
    vp[0] = vs[0] + av0;
    vp[1] = vs[1] + av1;
    vp[2] = vs[2] + av2;
}

// ---------------- update stage 1 ----------------
constexpr int TA = 8;
__global__ void __launch_bounds__(128)
upd1_kernel(const float* __restrict__ U, const float* __restrict__ Vw, int sel) {
    __shared__ __align__(16) float v_s[TA * 384];
    int t = threadIdx.x;
    int n0 = blockIdx.x * TA;
    const float* vcur = sel ? g_v1 : g_v0;

    for (int i = t; i < TA * 384; i += 128) {
        size_t gi = (size_t)n0 * 384 + i;
        v_s[i] = (gi < (size_t)NN * 384) ? vcur[gi] : 0.f;
    }
    __syncthreads();

    float uv[TA][3], vv[TA][3];
    #pragma unroll
    for (int a = 0; a < TA; a++)
        #pragma unroll
        for (int d = 0; d < 3; d++) { uv[a][d] = 0.f; vv[a][d] = 0.f; }

    for (int f4 = 0; f4 < 32; f4++) {
        float u0 = U[(f4 * 4 + 0) * 128 + t];
        float u1 = U[(f4 * 4 + 1) * 128 + t];
        float u2 = U[(f4 * 4 + 2) * 128 + t];
        float u3 = U[(f4 * 4 + 3) * 128 + t];
        float w0 = Vw[(f4 * 4 + 0) * 128 + t];
        float w1 = Vw[(f4 * 4 + 1) * 128 + t];
        float w2 = Vw[(f4 * 4 + 2) * 128 + t];
        float w3 = Vw[(f4 * 4 + 3) * 128 + t];
        #pragma unroll
        for (int a = 0; a < TA; a++) {
            const float4* vp = reinterpret_cast<const float4*>(&v_s[a * 384 + f4 * 12]);
            float4 p0 = vp[0], p1 = vp[1], p2 = vp[2];
            uv[a][0] = fmaf(p0.x, u0, fmaf(p0.w, u1, fmaf(p1.z, u2, fmaf(p2.y, u3, uv[a][0]))));
            uv[a][1] = fmaf(p0.y, u0, fmaf(p1.x, u1, fmaf(p1.w, u2, fmaf(p2.z, u3, uv[a][1]))));
            uv[a][2] = fmaf(p0.z, u0, fmaf(p1.y, u1, fmaf(p2.x, u2, fmaf(p2.w, u3, uv[a][2]))));
            vv[a][0] = fmaf(p0.x, w0, fmaf(p0.w, w1, fmaf(p1.z, w2, fmaf(p2.y, w3, vv[a][0]))));
            vv[a][1] = fmaf(p0.y, w0, fmaf(p1.x, w1, fmaf(p1.w, w2, fmaf(p2.z, w3, vv[a][1]))));
            vv[a][2] = fmaf(p0.z, w0, fmaf(p1.y, w1, fmaf(p2.x, w2, fmaf(p2.w, w3, vv[a][2]))));
        }
    }

    #pragma unroll
    for (int a = 0; a < TA; a++) {
        int n = n0 + a;
        if (n >= NN) break;
        float dt = uv[a][0] * vv[a][0] + uv[a][1] * vv[a][1] + uv[a][2] * vv[a][2];
        float vn = sqrtf(vv[a][0] * vv[a][0] + vv[a][1] * vv[a][1] + vv[a][2] * vv[a][2] + EPS3);
        g_uv[(size_t)n * 384 + 3 * t + 0] = uv[a][0];
        g_uv[(size_t)n * 384 + 3 * t + 1] = uv[a][1];
        g_uv[(size_t)n * 384 + 3 * t + 2] = uv[a][2];
        g_dot[(size_t)n * 128 + t] = dt;
        g_stk[(size_t)n * 256 + t] = g_s[(size_t)n * 128 + t];
        g_stk[(size_t)n * 256 + 128 + t] = vn;
    }
}

// ---------------- update apply ----------------
__global__ void apply_kernel(int sel) {
    int i = blockIdx.x * blockDim.x + threadIdx.x;
    if (i >= NN * 128) return;
    int n = i >> 7, g = i & 127;
    float avv = g_spl[(size_t)n * 384 + g];
    float asv = g_spl[(size_t)n * 384 + 128 + g];
    float ass = g_spl[(size_t)n * 384 + 256 + g];
    float* v = (sel ? g_v1 : g_v0) + (size_t)n * 384 + 3 * g;
    const float* uv = g_uv + (size_t)n * 384 + 3 * g;
    v[0] += uv[0] * avv;
    v[1] += uv[1] * avv;
    v[2] += uv[2] * avv;
    g_s[i] += g_dot[i] * asv + ass;
}

// ================ HMMA fused readout ================
constexpr int HP2 = 136;
__global__ void __launch_bounds__(256)
readout_mma(const float* __restrict__ W1, const float* __restrict__ b1,
            const float* __restrict__ w2, const float* __restrict__ b2,
            const int* __restrict__ nbrs, float* __restrict__ out) {
    extern __shared__ __align__(16) __half hsm[];
    __half* Ah = hsm;
    __half* Al = Ah + 128 * HP2;
    __half* Bh = Al + 128 * HP2;
    __half* Bl = Bh + 128 * HP2;
    __shared__ float red[128][2];

    int tid = threadIdx.x;
    int wid = tid >> 5, lane = tid & 31;
    int g = lane >> 2, tq = lane & 3;
    int m0 = (wid & 3) * 32;
    int n0w = (wid >> 2) * 64;
    int nw = wid >> 2;
    int e0 = blockIdx.x * 128;

    for (int idx = tid; idx < 128 * 32; idx += 256) {
        int e = idx >> 5, k = (idx & 31) * 4;
        float4 a = *(const float4*)&g_eij[(size_t)(e0 + e) * 128 + k];
        float x[4] = {a.x, a.y, a.z, a.w};
        #pragma unroll
        for (int j = 0; j < 4; j++) {
            __half hi, lo;
            split_h(x[j], hi, lo);
            Ah[e * HP2 + k + j] = hi;
            Al[e * HP2 + k + j] = lo;
        }
    }

    float rs[2][2] = {{0.f, 0.f}, {0.f, 0.f}};

    for (int nc = 0; nc < 2; nc++) {
        __syncthreads();
        for (int idx = tid; idx < 128 * 32; idx += 256) {
            int n = idx & 127, k = (idx >> 7) * 4;
            #pragma unroll
            for (int j = 0; j < 4; j++) {
                float w = W1[(size_t)(k + j) * 256 + nc * 128 + n];
                __half hi, lo;
                split_h(w, hi, lo);
                Bh[n * HP2 + k + j] = hi;
                Bl[n * HP2 + k + j] = lo;
            }
        }
        __syncthreads();

        float acc[2][8][4];
        #pragma unroll
        for (int mi = 0; mi < 2; mi++)
            #pragma unroll
            for (int ni = 0; ni < 8; ni++)
                #pragma unroll
                for (int j = 0; j < 4; j++) acc[mi][ni][j] = 0.f;

        #pragma unroll
        for (int ks = 0; ks < 8; ks++) {
            int kl = ks * 16;
            unsigned ah[2][4], al[2][4];
            #pragma unroll
            for (int mi = 0; mi < 2; mi++) {
                int r = m0 + mi * 16;
                ah[mi][0] = *(const unsigned*)&Ah[(r + g) * HP2 + kl + 2 * tq];
                ah[mi][1] = *(const unsigned*)&Ah[(r + g + 8) * HP2 + kl + 2 * tq];
                ah[mi][2] = *(const unsigned*)&Ah[(r + g) * HP2 + kl + 8 + 2 * tq];
                ah[mi][3] = *(const unsigned*)&Ah[(r + g + 8) * HP2 + kl + 8 + 2 * tq];
                al[mi][0] = *(const unsigned*)&Al[(r + g) * HP2 + kl + 2 * tq];
                al[mi][1] = *(const unsigned*)&Al[(r + g + 8) * HP2 + kl + 2 * tq];
                al[mi][2] = *(const unsigned*)&Al[(r + g) * HP2 + kl + 8 + 2 * tq];
                al[mi][3] = *(const unsigned*)&Al[(r + g + 8) * HP2 + kl + 8 + 2 * tq];
            }
            #pragma unroll
            for (int ni = 0; ni < 8; ni++) {
                int n = n0w + ni * 8 + g;
                unsigned bh[2], bl[2];
                bh[0] = *(const unsigned*)&Bh[n * HP2 + kl + 2 * tq];
                bh[1] = *(const unsigned*)&Bh[n * HP2 + kl + 8 + 2 * tq];
                bl[0] = *(const unsigned*)&Bl[n * HP2 + kl + 2 * tq];
                bl[1] = *(const unsigned*)&Bl[n * HP2 + kl + 8 + 2 * tq];
                #pragma unroll
                for (int mi = 0; mi < 2; mi++) {
                    hmma(acc[mi][ni], ah[mi], bh);
                    hmma(acc[mi][ni], ah[mi], bl);
                    hmma(acc[mi][ni], al[mi], bh);
                }
            }
        }

        #pragma unroll
        for (int mi = 0; mi < 2; mi++) {
            #pragma unroll
            for (int ni = 0; ni < 8; ni++) {
                int c = nc * 128 + n0w + ni * 8 + 2 * tq;
                float2 bb = *(const float2*)&b1[c];
                float2 ww = *(const float2*)&w2[c];
                rs[mi][0] += swish(acc[mi][ni][0] + bb.x) * ww.x
                           + swish(acc[mi][ni][1] + bb.y) * ww.y;
                rs[mi][1] += swish(acc[mi][ni][2] + bb.x) * ww.x
                           + swish(acc[mi][ni][3] + bb.y) * ww.y;
            }
        }
    }

    #pragma unroll
    for (int mi = 0; mi < 2; mi++) {
        #pragma unroll
        for (int h = 0; h < 2; h++) {
            float v = rs[mi][h];
            v += __shfl_xor_sync(0xffffffff, v, 1);
            v += __shfl_xor_sync(0xffffffff, v, 2);
            rs[mi][h] = v;
        }
    }
    if (tq == 0) {
        red[m0 + g][nw]          = rs[0][0];
        red[m0 + g + 8][nw]      = rs[0][1];
        red[m0 + 16 + g][nw]     = rs[1][0];
        red[m0 + 16 + g + 8][nw] = rs[1][1];
    }
    __syncthreads();

    if (tid < 128) {
        int e = e0 + tid;
        float s = red[tid][0] + red[tid][1] + b2[0];
        int src = nbrs[2 * e], dst = nbrs[2 * e + 1];
        float fx = s * g_unit[(size_t)e * 3 + 0];
        float fy = s * g_unit[(size_t)e * 3 + 1];
        float fz = s * g_unit[(size_t)e * 3 + 2];
        atomicAdd(&out[src * 3 + 0], fx);
        atomicAdd(&out[src * 3 + 1], fy);
        atomicAdd(&out[src * 3 + 2], fz);
        atomicAdd(&out[dst * 3 + 0], -fx);
        atomicAdd(&out[dst * 3 + 1], -fy);
        atomicAdd(&out[dst * 3 + 2], -fz);
    }
}

// ---------------- host launcher ----------------
extern "C" void kernel_launch(void* const* d_in, const int* in_sizes, int n_in,
                              void* d_out, int out_size) {
    const float* xyz     = (const float*)d_in[0];
    const int*   z       = (const int*)  d_in[1];
    const int*   nbrs    = (const int*)  d_in[2];
    const float* emb     = (const float*)d_in[3];
    const float* de_w    = (const float*)d_in[4];
    const float* de_b    = (const float*)d_in[5];
    const float* msg_w1  = (const float*)d_in[6];
    const float* msg_b1  = (const float*)d_in[7];
    const float* msg_w2  = (const float*)d_in[8];
    const float* msg_b2  = (const float*)d_in[9];
    const float* msg_dw  = (const float*)d_in[10];
    const float* msg_db  = (const float*)d_in[11];
    const float* upd_u   = (const float*)d_in[12];
    const float* upd_v   = (const float*)d_in[13];
    const float* upd_w1  = (const float*)d_in[14];
    const float* upd_b1  = (const float*)d_in[15];
    const float* upd_w2  = (const float*)d_in[16];
    const float* upd_b2  = (const float*)d_in[17];
    const float* edge_w1 = (const float*)d_in[18];
    const float* edge_b1 = (const float*)d_in[19];
    const float* edge_w2 = (const float*)d_in[20];
    const float* edge_b2 = (const float*)d_in[21];
    const float* ro_w1   = (const float*)d_in[22];
    const float* ro_b1   = (const float*)d_in[23];
    const float* ro_w2   = (const float*)d_in[24];
    const float* ro_b2   = (const float*)d_in[25];
    float* out = (float*)d_out;

    float *p_rbf, *p_env, *p_eij, *p_s, *p_phi, *p_h1, *p_stk, *p_spl;
    float *p_tbuf[3];
    cudaGetSymbolAddress((void**)&p_rbf,  g_rbf);
    cudaGetSymbolAddress((void**)&p_env,  g_env);
    cudaGetSymbolAddress((void**)&p_eij,  g_eij);
    cudaGetSymbolAddress((void**)&p_s,    g_s);
    cudaGetSymbolAddress((void**)&p_phi,  g_phi);
    cudaGetSymbolAddress((void**)&p_h1,   g_h1);
    cudaGetSymbolAddress((void**)&p_stk,  g_stk);
    cudaGetSymbolAddress((void**)&p_spl,  g_spl);
    cudaGetSymbolAddress((void**)&p_tbuf[0], g_tA);
    cudaGetSymbolAddress((void**)&p_tbuf[1], g_tB);
    cudaGetSymbolAddress((void**)&p_tbuf[2], g_tC);

    // lazy side-stream/events (created on first (correctness) call, reused in capture)
    static cudaStream_t s_side = nullptr;
    static cudaEvent_t ev_fork[2], ev_join[2];
    if (s_side == nullptr) {
        cudaStreamCreateWithFlags(&s_side, cudaStreamNonBlocking);
        for (int i = 0; i < 2; i++) {
            cudaEventCreateWithFlags(&ev_fork[i], cudaEventDisableTiming);
            cudaEventCreateWithFlags(&ev_join[i], cudaEventDisableTiming);
        }
    }

    const int SMEM_E = (2 * 128 + 2 * 128) * HP * 2;  // 73728 (MT=128)
    const int SMEM_N = (2 * 64 + 2 * 128) * HP * 2;   // 55296 (MT=64)
    const int SMEM_RO = 4 * 128 * HP2 * 2;            // 139264
    cudaFuncSetAttribute(hmma_gemm<64, 128, false, true,  false, false>,
                         cudaFuncAttributeMaxDynamicSharedMemorySize, SMEM_N);
    cudaFuncSetAttribute(hmma_gemm<64, 128, false, false, false, false>,
                         cudaFuncAttributeMaxDynamicSharedMemorySize, SMEM_N);
    cudaFuncSetAttribute(hmma_gemm<64, 256, false, true,  false, false>,
                         cudaFuncAttributeMaxDynamicSharedMemorySize, SMEM_N);
    cudaFuncSetAttribute(hmma_gemm<128, 256, true, false, true,  false>,
                         cudaFuncAttributeMaxDynamicSharedMemorySize, SMEM_E);
    cudaFuncSetAttribute(hmma_gemm<128, 256, true, false, false, true>,
                         cudaFuncAttributeMaxDynamicSharedMemorySize, SMEM_E);
    cudaFuncSetAttribute(readout_mma,
                         cudaFuncAttributeMaxDynamicSharedMemorySize, SMEM_RO);

    const int gN = (NN + 63) / 64;    // 313  (node GEMMs, MT=64)
    const int gE = EE / 128;          // 2500 (edge GEMMs, MT=128)

    init_kernel<<<2048, 256>>>(emb, z, out);
    prep_kernel<<<(EE + 255) / 256, 256>>>(xyz, nbrs);

    // CSR build
    zero_rowptr<<<(NN + 256) / 256, 256>>>();
    hist_kernel<<<(EE + 255) / 256, 256>>>(nbrs);
    scan_kernel<<<1, 1024>>>();      // also fills g_cursor
    scatter_kernel<<<(EE + 255) / 256, 256>>>(nbrs);

    for (int l = 0; l < 3; l++) {
        int sel = l & 1;
        int cur = sel ^ 1;
        float* p_t = p_tbuf[l];

        // phi = swish(s @ msg_w1 + b1) @ msg_w2 + b2
        hmma_gemm<64, 128, false, true, false, false><<<dim3(gN, 1), 256, SMEM_N>>>(
            p_s, msg_w1 + l * 128 * 128, 128, msg_b1 + l * 128, 1.f, p_h1, nullptr, NN,
            nullptr, nullptr, nullptr, nullptr);
        hmma_gemm<64, 128, false, false, false, false><<<dim3(gN, 3), 256, SMEM_N>>>(
            p_h1, msg_w2 + l * 128 * 384, 384, msg_b2 + l * 384, 1.f, p_phi, nullptr, NN,
            nullptr, nullptr, nullptr, nullptr);

        // CSR message pass (smem-staged)
        msg2_kernel<<<NN, 128>>>(nbrs, msg_dw + l * RB * 384, msg_db + l * 384, sel);

        // update block
        upd1_kernel<<<(NN + TA - 1) / TA, 128>>>(upd_u + l * 128 * 128,
                                                 upd_v + l * 128 * 128, cur);
        hmma_gemm<64, 256, false, true, false, false><<<dim3(gN, 1), 256, SMEM_N>>>(
            p_stk, upd_w1 + l * 256 * 128, 128, upd_b1 + l * 128, 1.f, p_h1, nullptr, NN,
            nullptr, nullptr, nullptr, nullptr);
        hmma_gemm<64, 128, false, false, false, false><<<dim3(gN, 3), 256, SMEM_N>>>(
            p_h1, upd_w2 + l * 128 * 384, 384, upd_b2 + l * 384, 1.f, p_spl, nullptr, NN,
            nullptr, nullptr, nullptr, nullptr);
        apply_kernel<<<(NN * 128 + 255) / 256, 256>>>(cur);

        // edge MLP (factored): t per node (layer-private buffer)
        hmma_gemm<64, 128, false, false, false, false><<<dim3(gN, 2), 256, SMEM_N>>>(
            p_s, edge_w1 + l * 128 * 256, 256, edge_b1 + l * 256, 0.5f, p_t, nullptr, NN,
            nullptr, nullptr, nullptr, nullptr);

        if (l < 2) {
            // fork: run edge2(l) on the side stream, overlapped with next layer's node work
            cudaEventRecord(ev_fork[l], 0);
            cudaStreamWaitEvent(s_side, ev_fork[l], 0);
            if (l == 0) {
                hmma_gemm<128, 256, true, false, false, true><<<dim3(gE, 1), 256, SMEM_E, s_side>>>(
                    p_t, edge_w2, 128, edge_b2, 1.f, p_eij, nbrs, EE,
                    p_rbf, p_env, de_w, de_b);
            } else {
                hmma_gemm<128, 256, true, false, true, false><<<dim3(gE, 1), 256, SMEM_E, s_side>>>(
                    p_t, edge_w2 + l * 256 * 128, 128, edge_b2 + l * 128, 1.f, p_eij, nbrs, EE,
                    nullptr, nullptr, nullptr, nullptr);
            }
            cudaEventRecord(ev_join[l], s_side);
        } else {
            // join: eij RMW ordering vs edge2(l=1) on the side stream
            cudaStreamWaitEvent(0, ev_join[1], 0);
            hmma_gemm<128, 256, true, false, true, false><<<dim3(gE, 1), 256, SMEM_E>>>(
                p_t, edge_w2 + l * 256 * 128, 128, edge_b2 + l * 128, 1.f, p_eij, nbrs, EE,
                nullptr, nullptr, nullptr, nullptr);
        }
    }

    // fused HMMA readout (main stream; ordered after edge2(l=2))
    readout_mma<<<gE, 256, SMEM_RO>>>(ro_w1, ro_b1, ro_w2, ro_b2, nbrs, out);

    (void)in_sizes; (void)n_in; (void)out_size;
}